// round 2
// baseline (speedup 1.0000x reference)
#include <cuda_runtime.h>
#include <cuda_bf16.h>
#include <math.h>

// Problem constants
#define B_SZ   2
#define S_LEN  2048
#define EMB    1024
#define NHEAD  16
#define HDIM   64
#define ROWS   (B_SZ * S_LEN)          // 4096

// Scratch (device globals -> no allocation)
__device__ float g_Q[B_SZ * NHEAD * S_LEN * HDIM];   // 4M floats
__device__ float g_K[B_SZ * NHEAD * S_LEN * HDIM];
__device__ float g_V[B_SZ * NHEAD * S_LEN * HDIM];
__device__ float g_CTX[ROWS * EMB];                  // 4M floats

// ---------------------------------------------------------------------------
// GEMM: C[M,N] = A[M,K] @ B[K,N] + bias[N]
// MODE 0: A = param, scatter output into g_Q/g_K/g_V  (QKV GEMM, N=3072)
// MODE 1: A = g_CTX, output row-major into C param    (proj GEMM)
// Tile 128x128x16, 256 threads, 8x8 per thread (split 4+4 fragments).
// ---------------------------------------------------------------------------
#define BM 128
#define BN 128
#define BK 16

template <int MODE>
__global__ void __launch_bounds__(256, 2)
gemm_kernel(const float* __restrict__ A_in, const float* __restrict__ Bw,
            const float* __restrict__ bias, float* __restrict__ C,
            int M, int N, int K)
{
    __shared__ float As[BK][BM];
    __shared__ float Bs[BK][BN];

    const float* A = (MODE == 1) ? g_CTX : A_in;

    const int tid = threadIdx.x;
    const int tx  = tid & 15;
    const int ty  = tid >> 4;
    const int m0  = blockIdx.y * BM;
    const int n0  = blockIdx.x * BN;

    float acc[8][8];
#pragma unroll
    for (int i = 0; i < 8; i++)
#pragma unroll
        for (int j = 0; j < 8; j++) acc[i][j] = 0.0f;

    for (int k0 = 0; k0 < K; k0 += BK) {
        // Load A tile 128x16 -> As transposed [k][m]
#pragma unroll
        for (int it = 0; it < 2; it++) {
            int id  = tid + it * 256;        // 0..511 float4 slots
            int row = id >> 2;               // 4 float4 per row (16 floats)
            int c4  = id & 3;
            float4 v = *(const float4*)(A + (size_t)(m0 + row) * K + k0 + c4 * 4);
            As[c4 * 4 + 0][row] = v.x;
            As[c4 * 4 + 1][row] = v.y;
            As[c4 * 4 + 2][row] = v.z;
            As[c4 * 4 + 3][row] = v.w;
        }
        // Load B tile 16x128 -> Bs row-major
#pragma unroll
        for (int it = 0; it < 2; it++) {
            int id  = tid + it * 256;
            int row = id >> 5;               // 32 float4 per row (128 floats)
            int c4  = id & 31;
            *(float4*)(&Bs[row][c4 * 4]) =
                *(const float4*)(Bw + (size_t)(k0 + row) * N + n0 + c4 * 4);
        }
        __syncthreads();

#pragma unroll
        for (int k = 0; k < BK; k++) {
            float a[8], b[8];
#pragma unroll
            for (int i = 0; i < 4; i++) {
                a[i]     = As[k][ty * 4 + i];
                a[i + 4] = As[k][64 + ty * 4 + i];
                b[i]     = Bs[k][tx * 4 + i];
                b[i + 4] = Bs[k][64 + tx * 4 + i];
            }
#pragma unroll
            for (int i = 0; i < 8; i++)
#pragma unroll
                for (int j = 0; j < 8; j++) acc[i][j] += a[i] * b[j];
        }
        __syncthreads();
    }

    // Epilogue
#pragma unroll
    for (int i = 0; i < 8; i++) {
        int row = m0 + ((i < 4) ? (ty * 4 + i) : (64 + ty * 4 + (i - 4)));
#pragma unroll
        for (int j = 0; j < 8; j++) {
            int col = n0 + ((j < 4) ? (tx * 4 + j) : (64 + tx * 4 + (j - 4)));
            float v = acc[i][j] + bias[col];
            if (MODE == 1) {
                C[(size_t)row * N + col] = v;
            } else {
                // scatter into Q/K/V [B,H,S,D]
                int which = col >> 10;       // 0:Q 1:K 2:V
                int e = col & 1023;
                int h = e >> 6;
                int d = e & 63;
                int b = row >> 11;           // /2048
                int s = row & 2047;
                float* dst = (which == 0) ? g_Q : (which == 1) ? g_K : g_V;
                dst[(((size_t)(b * NHEAD + h)) * S_LEN + s) * HDIM + d] = v;
            }
        }
    }
}

// ---------------------------------------------------------------------------
// Flash attention (causal). Tiles: 64 queries x 64 keys, D=64.
// 256 threads: (ty,tx) = 16x16, each thread 4x4 micro-tile.
// Smem: Qt[d][q], Kt[d][k] (transposed), Vs[k][d], Pt[k][q]; stride 68.
// Writes g_CTX directly (device symbol — NEVER pass __device__ globals as
// host-side kernel args: on GB300/ATS that silently writes host memory).
// ---------------------------------------------------------------------------
#define FPAD 68
#define FT   64

__global__ void __launch_bounds__(256, 2)
flash_kernel()
{
    extern __shared__ float sm[];
    float* Qt = sm;                     // [64][68]  Qt[d*68+q]
    float* Kt = sm + FT * FPAD;         // [64][68]  Kt[d*68+k]
    float* Vs = sm + 2 * FT * FPAD;     // [64][68]  Vs[k*68+d]
    float* Pt = sm + 3 * FT * FPAD;     // [64][68]  Pt[k*68+q]

    const int tid = threadIdx.x;
    const int tx  = tid & 15;
    const int ty  = tid >> 4;
    const int qt  = blockIdx.x;         // 0..31
    const int bh  = blockIdx.y;         // 0..31
    const int q0  = qt * FT;

    const float* Qg = g_Q + (size_t)bh * S_LEN * HDIM;
    const float* Kg = g_K + (size_t)bh * S_LEN * HDIM;
    const float* Vg = g_V + (size_t)bh * S_LEN * HDIM;

    // Load Q tile transposed
#pragma unroll
    for (int it = 0; it < 4; it++) {
        int id  = tid + it * 256;       // 0..1023 float4 slots
        int row = id >> 4;              // 16 float4 per row of 64
        int c4  = id & 15;
        float4 v = *(const float4*)(Qg + (size_t)(q0 + row) * HDIM + c4 * 4);
        Qt[(c4 * 4 + 0) * FPAD + row] = v.x;
        Qt[(c4 * 4 + 1) * FPAD + row] = v.y;
        Qt[(c4 * 4 + 2) * FPAD + row] = v.z;
        Qt[(c4 * 4 + 3) * FPAD + row] = v.w;
    }

    float m_r[4], l_r[4], acc[4][4];
#pragma unroll
    for (int i = 0; i < 4; i++) {
        m_r[i] = -1e30f;
        l_r[i] = 0.0f;
#pragma unroll
        for (int j = 0; j < 4; j++) acc[i][j] = 0.0f;
    }
    const float scale = 0.125f;   // 1/sqrt(64)

    for (int kt = 0; kt <= qt; kt++) {
        __syncthreads();   // prev PV reads done before overwriting K/V
        const int k0 = kt * FT;
#pragma unroll
        for (int it = 0; it < 4; it++) {
            int id  = tid + it * 256;
            int row = id >> 4;
            int c4  = id & 15;
            float4 kv = *(const float4*)(Kg + (size_t)(k0 + row) * HDIM + c4 * 4);
            Kt[(c4 * 4 + 0) * FPAD + row] = kv.x;
            Kt[(c4 * 4 + 1) * FPAD + row] = kv.y;
            Kt[(c4 * 4 + 2) * FPAD + row] = kv.z;
            Kt[(c4 * 4 + 3) * FPAD + row] = kv.w;
            float4 vv = *(const float4*)(Vg + (size_t)(k0 + row) * HDIM + c4 * 4);
            *(float4*)(&Vs[row * FPAD + c4 * 4]) = vv;
        }
        __syncthreads();

        // S = Q K^T  (4x4 per thread)
        float s[4][4];
#pragma unroll
        for (int i = 0; i < 4; i++)
#pragma unroll
            for (int j = 0; j < 4; j++) s[i][j] = 0.0f;

        for (int kk = 0; kk < FT; kk++) {
            float a[4], b[4];
#pragma unroll
            for (int i = 0; i < 4; i++) a[i] = Qt[kk * FPAD + ty * 4 + i];
#pragma unroll
            for (int j = 0; j < 4; j++) b[j] = Kt[kk * FPAD + tx * 4 + j];
#pragma unroll
            for (int i = 0; i < 4; i++)
#pragma unroll
                for (int j = 0; j < 4; j++) s[i][j] += a[i] * b[j];
        }

        const bool diag = (kt == qt);
#pragma unroll
        for (int i = 0; i < 4; i++) {
            int qidx = q0 + ty * 4 + i;
#pragma unroll
            for (int j = 0; j < 4; j++) {
                s[i][j] *= scale;
                if (diag && (k0 + tx * 4 + j) > qidx) s[i][j] = -1e30f;
            }
        }

        // online softmax per row
#pragma unroll
        for (int i = 0; i < 4; i++) {
            float mx = fmaxf(fmaxf(s[i][0], s[i][1]), fmaxf(s[i][2], s[i][3]));
#pragma unroll
            for (int off = 8; off >= 1; off >>= 1)
                mx = fmaxf(mx, __shfl_xor_sync(0xffffffffu, mx, off));
            float m_new = fmaxf(m_r[i], mx);
            float alpha = __expf(m_r[i] - m_new);
            float sum = 0.0f;
#pragma unroll
            for (int j = 0; j < 4; j++) {
                float p = __expf(s[i][j] - m_new);
                s[i][j] = p;
                sum += p;
            }
#pragma unroll
            for (int off = 8; off >= 1; off >>= 1)
                sum += __shfl_xor_sync(0xffffffffu, sum, off);
            l_r[i] = l_r[i] * alpha + sum;
            m_r[i] = m_new;
#pragma unroll
            for (int j = 0; j < 4; j++) acc[i][j] *= alpha;
        }

        // stash P transposed
#pragma unroll
        for (int i = 0; i < 4; i++)
#pragma unroll
            for (int j = 0; j < 4; j++)
                Pt[(tx * 4 + j) * FPAD + ty * 4 + i] = s[i][j];
        __syncthreads();

        // O += P V
        for (int kk = 0; kk < FT; kk++) {
            float p[4], v[4];
#pragma unroll
            for (int i = 0; i < 4; i++) p[i] = Pt[kk * FPAD + ty * 4 + i];
#pragma unroll
            for (int j = 0; j < 4; j++) v[j] = Vs[kk * FPAD + tx * 4 + j];
#pragma unroll
            for (int i = 0; i < 4; i++)
#pragma unroll
                for (int j = 0; j < 4; j++) acc[i][j] += p[i] * v[j];
        }
    }

    // write ctx [B,S,E] directly into device-global g_CTX
    const int b = bh >> 4, h = bh & 15;
#pragma unroll
    for (int i = 0; i < 4; i++) {
        float inv = 1.0f / l_r[i];
        int q = q0 + ty * 4 + i;
#pragma unroll
        for (int j = 0; j < 4; j++) {
            g_CTX[((size_t)(b * S_LEN + q)) * EMB + h * HDIM + tx * 4 + j] =
                acc[i][j] * inv;
        }
    }
}

// ---------------------------------------------------------------------------
extern "C" void kernel_launch(void* const* d_in, const int* in_sizes, int n_in,
                              void* d_out, int out_size)
{
    const float* x      = (const float*)d_in[0];  // [2,2048,1024]
    const float* w_attn = (const float*)d_in[1];  // [1024,3072]
    const float* b_attn = (const float*)d_in[2];  // [3072]
    const float* w_proj = (const float*)d_in[3];  // [1024,1024]
    const float* b_proj = (const float*)d_in[4];  // [1024]
    float* out = (float*)d_out;                   // [2,2048,1024]

    // 1) QKV GEMM + scatter
    {
        dim3 grid(3 * EMB / BN, ROWS / BM);       // (24, 32)
        gemm_kernel<0><<<grid, 256>>>(x, w_attn, b_attn, nullptr,
                                      ROWS, 3 * EMB, EMB);
    }

    // 2) causal flash attention (writes g_CTX internally)
    {
        static int smem_set = 0;
        int smem = 4 * FT * FPAD * (int)sizeof(float);   // 69632 B
        if (!smem_set) {
            cudaFuncSetAttribute(flash_kernel,
                                 cudaFuncAttributeMaxDynamicSharedMemorySize, smem);
            smem_set = 1;
        }
        dim3 grid(S_LEN / FT, B_SZ * NHEAD);      // (32, 32)
        flash_kernel<<<grid, 256, smem>>>();
    }

    // 3) projection GEMM (reads g_CTX internally)
    {
        dim3 grid(EMB / BN, ROWS / BM);           // (8, 32)
        gemm_kernel<1><<<grid, 256>>>(nullptr, w_proj, b_proj, out,
                                      ROWS, EMB, EMB);
    }
}

// round 4
// speedup vs baseline: 1.4030x; 1.4030x over previous
#include <cuda_runtime.h>
#include <cuda_bf16.h>
#include <cstdint>
#include <math.h>

// Problem constants
#define B_SZ   2
#define S_LEN  2048
#define EMB    1024
#define NHEAD  16
#define HDIM   64
#define ROWS   (B_SZ * S_LEN)          // 4096

// Scratch (device globals -> no allocation)
__device__ float g_Q[B_SZ * NHEAD * S_LEN * HDIM];
__device__ float g_K[B_SZ * NHEAD * S_LEN * HDIM];
__device__ float g_V[B_SZ * NHEAD * S_LEN * HDIM];
__device__ float g_CTX[ROWS * EMB];
__device__ float g_Xr[ROWS * EMB];       // tf32-rounded x
__device__ float g_WaT[3 * EMB * EMB];   // w_attn^T  [3072][1024], tf32-rounded
__device__ float g_WpT[EMB * EMB];       // w_proj^T  [1024][1024], tf32-rounded

// ---------------------------------------------------------------------------
// Helpers
// ---------------------------------------------------------------------------
__device__ __forceinline__ uint32_t smem_u32(const void* p) {
    uint32_t a;
    asm("{ .reg .u64 t; cvta.to.shared.u64 t, %1; cvt.u32.u64 %0, t; }"
        : "=r"(a) : "l"(p));
    return a;
}
__device__ __forceinline__ float cvt_tf32(float v) {
    float o;
    asm("cvt.rna.tf32.f32 %0, %1;" : "=f"(o) : "f"(v));
    return o;
}
__device__ __forceinline__ void cp16(uint32_t smaddr, const void* gaddr) {
    asm volatile("cp.async.cg.shared.global [%0], [%1], 16;"
                 :: "r"(smaddr), "l"(gaddr) : "memory");
}
__device__ __forceinline__ void mma_tf32(float& d0, float& d1, float& d2, float& d3,
                                         uint32_t a0, uint32_t a1, uint32_t a2, uint32_t a3,
                                         uint32_t b0, uint32_t b1) {
    asm volatile(
        "mma.sync.aligned.m16n8k8.row.col.f32.tf32.tf32.f32 "
        "{%0,%1,%2,%3},{%4,%5,%6,%7},{%8,%9},{%0,%1,%2,%3};"
        : "+f"(d0), "+f"(d1), "+f"(d2), "+f"(d3)
        : "r"(a0), "r"(a1), "r"(a2), "r"(a3), "r"(b0), "r"(b1));
}

// ---------------------------------------------------------------------------
// Pre-round x to tf32 (unbiased rna) into g_Xr
// ---------------------------------------------------------------------------
__global__ void round_x(const float* __restrict__ x)
{
    int i = (blockIdx.x * 256 + threadIdx.x) * 4;
    float4 v = *(const float4*)(x + i);
    v.x = cvt_tf32(v.x); v.y = cvt_tf32(v.y);
    v.z = cvt_tf32(v.z); v.w = cvt_tf32(v.w);
    *(float4*)(g_Xr + i) = v;
}

// ---------------------------------------------------------------------------
// Weight transpose with tf32 pre-rounding: src[K][N] -> dst[N][K]
// ---------------------------------------------------------------------------
template <int W>
__global__ void transpose_tf32(const float* __restrict__ src, int K, int N)
{
    __shared__ float t[32][33];
    float* dst = (W == 0) ? g_WaT : g_WpT;
    const int x = threadIdx.x, y = threadIdx.y;
    const int n0 = blockIdx.x * 32, k0 = blockIdx.y * 32;
#pragma unroll
    for (int i = 0; i < 4; i++) {
        float v = src[(size_t)(k0 + y + i * 8) * N + n0 + x];
        t[y + i * 8][x] = cvt_tf32(v);
    }
    __syncthreads();
#pragma unroll
    for (int i = 0; i < 4; i++)
        dst[(size_t)(n0 + y + i * 8) * K + k0 + x] = t[x][y + i * 8];
}

// ---------------------------------------------------------------------------
// tf32 mma.sync GEMM: D[M,N] = A[M,1024] @ BT[N,1024]^T + bias[N]
// CTA 128x128, 4 warps (2x2 of 64x64), K-chunk 32, cp.async double buffer.
// MODE 0: A = g_Xr, BT = g_WaT, scatter to g_Q/g_K/g_V
// MODE 1: A = g_CTX, BT = g_WpT, write Cout row-major
// ---------------------------------------------------------------------------
#define TM 128
#define TN 128
#define TK 32
#define PAD 36
#define ABUF (TM * PAD)                 // 4608 floats
#define NSTAGE (EMB / TK)               // 32
#define GSMEM_BYTES (2 * 2 * ABUF * 4)  // 73728

template <int MODE>
__global__ void __launch_bounds__(128)
gemm_tc(const float* __restrict__ bias, float* __restrict__ Cout)
{
    extern __shared__ float smf[];
    const int tid  = threadIdx.x;
    const int wid  = tid >> 5;
    const int lane = tid & 31;
    const int gid  = lane >> 2;          // 0..7
    const int tig  = lane & 3;           // 0..3
    const int warp_m = (wid >> 1) * 64;
    const int warp_n = (wid & 1) * 64;
    const int m0 = blockIdx.y * TM;
    const int n0 = blockIdx.x * TN;

    const float* A  = (MODE == 1) ? g_CTX : g_Xr;
    const float* BT = (MODE == 1) ? g_WpT : g_WaT;

    float acc[4][8][4];
#pragma unroll
    for (int mt = 0; mt < 4; mt++)
#pragma unroll
        for (int nt = 0; nt < 8; nt++)
#pragma unroll
            for (int r = 0; r < 4; r++) acc[mt][nt][r] = 0.0f;

#define ISSUE(s_)                                                              \
    {                                                                          \
        float* dA = smf + ((s_) & 1) * (2 * ABUF);                             \
        float* dB = dA + ABUF;                                                 \
        const float* ga = A + (size_t)(m0 + tid) * EMB + (s_) * TK;            \
        const float* gb = BT + (size_t)(n0 + tid) * EMB + (s_) * TK;           \
        uint32_t sa = smem_u32(dA + tid * PAD);                                \
        uint32_t sbb = smem_u32(dB + tid * PAD);                               \
        _Pragma("unroll")                                                      \
        for (int c = 0; c < 8; c++) {                                          \
            cp16(sa + c * 16, ga + c * 4);                                     \
            cp16(sbb + c * 16, gb + c * 4);                                    \
        }                                                                      \
        asm volatile("cp.async.commit_group;" ::: "memory");                   \
    }

    ISSUE(0);
    for (int s = 0; s < NSTAGE; s++) {
        if (s + 1 < NSTAGE) {
            ISSUE(s + 1);
            asm volatile("cp.async.wait_group 1;" ::: "memory");
        } else {
            asm volatile("cp.async.wait_group 0;" ::: "memory");
        }
        __syncthreads();

        const uint32_t* As = (const uint32_t*)(smf + (s & 1) * (2 * ABUF));
        const uint32_t* Bs = As + ABUF;
#pragma unroll
        for (int kk = 0; kk < 4; kk++) {
            uint32_t af[4][4], bf[8][2];
            const int kb = kk * 8 + tig;
#pragma unroll
            for (int mt = 0; mt < 4; mt++) {
                const int m = warp_m + mt * 16 + gid;
                af[mt][0] = As[m * PAD + kb];
                af[mt][1] = As[(m + 8) * PAD + kb];
                af[mt][2] = As[m * PAD + kb + 4];
                af[mt][3] = As[(m + 8) * PAD + kb + 4];
            }
#pragma unroll
            for (int nt = 0; nt < 8; nt++) {
                const int n = warp_n + nt * 8 + gid;
                bf[nt][0] = Bs[n * PAD + kb];
                bf[nt][1] = Bs[n * PAD + kb + 4];
            }
#pragma unroll
            for (int mt = 0; mt < 4; mt++)
#pragma unroll
                for (int nt = 0; nt < 8; nt++)
                    mma_tf32(acc[mt][nt][0], acc[mt][nt][1],
                             acc[mt][nt][2], acc[mt][nt][3],
                             af[mt][0], af[mt][1], af[mt][2], af[mt][3],
                             bf[nt][0], bf[nt][1]);
        }
        __syncthreads();
    }
#undef ISSUE

    // Epilogue. Thread owns rows (gid, gid+8) x cols (tig*2, tig*2+1) per tile.
#pragma unroll
    for (int mt = 0; mt < 4; mt++) {
        const int r0 = m0 + warp_m + mt * 16 + gid;
        const int r1 = r0 + 8;
#pragma unroll
        for (int nt = 0; nt < 8; nt++) {
            const int nb = n0 + warp_n + nt * 8;       // 8-wide tile base
            const int c  = nb + tig * 2;
            const float2 bv = *(const float2*)(bias + c);
            float2 o0, o1;
            o0.x = acc[mt][nt][0] + bv.x;
            o0.y = acc[mt][nt][1] + bv.y;
            o1.x = acc[mt][nt][2] + bv.x;
            o1.y = acc[mt][nt][3] + bv.y;
            if (MODE == 1) {
                *(float2*)(Cout + (size_t)r0 * EMB + c) = o0;
                *(float2*)(Cout + (size_t)r1 * EMB + c) = o1;
            } else {
                const int which = nb >> 10;
                const int e  = nb & 1023;
                const int h  = e >> 6;
                const int dd = (e & 63) + tig * 2;
                float* dst = (which == 0) ? g_Q : (which == 1) ? g_K : g_V;
                const int b0i = r0 >> 11, s0i = r0 & 2047;
                const int b1i = r1 >> 11, s1i = r1 & 2047;
                *(float2*)(dst + (((size_t)(b0i * NHEAD + h)) * S_LEN + s0i) * HDIM + dd) = o0;
                *(float2*)(dst + (((size_t)(b1i * NHEAD + h)) * S_LEN + s1i) * HDIM + dd) = o1;
            }
        }
    }
}

// ---------------------------------------------------------------------------
// Flash attention (causal), fp32 — verified correct in R2.
// Epilogue now tf32-rounds ctx (it feeds the tf32 proj GEMM anyway).
// ---------------------------------------------------------------------------
#define FPAD 68
#define FT   64

__global__ void __launch_bounds__(256, 2)
flash_kernel()
{
    extern __shared__ float sm[];
    float* Qt = sm;
    float* Kt = sm + FT * FPAD;
    float* Vs = sm + 2 * FT * FPAD;
    float* Pt = sm + 3 * FT * FPAD;

    const int tid = threadIdx.x;
    const int tx  = tid & 15;
    const int ty  = tid >> 4;
    const int qt  = blockIdx.x;
    const int bh  = blockIdx.y;
    const int q0  = qt * FT;

    const float* Qg = g_Q + (size_t)bh * S_LEN * HDIM;
    const float* Kg = g_K + (size_t)bh * S_LEN * HDIM;
    const float* Vg = g_V + (size_t)bh * S_LEN * HDIM;

#pragma unroll
    for (int it = 0; it < 4; it++) {
        int id  = tid + it * 256;
        int row = id >> 4;
        int c4  = id & 15;
        float4 v = *(const float4*)(Qg + (size_t)(q0 + row) * HDIM + c4 * 4);
        Qt[(c4 * 4 + 0) * FPAD + row] = v.x;
        Qt[(c4 * 4 + 1) * FPAD + row] = v.y;
        Qt[(c4 * 4 + 2) * FPAD + row] = v.z;
        Qt[(c4 * 4 + 3) * FPAD + row] = v.w;
    }

    float m_r[4], l_r[4], acc[4][4];
#pragma unroll
    for (int i = 0; i < 4; i++) {
        m_r[i] = -1e30f;
        l_r[i] = 0.0f;
#pragma unroll
        for (int j = 0; j < 4; j++) acc[i][j] = 0.0f;
    }
    const float scale = 0.125f;

    for (int kt = 0; kt <= qt; kt++) {
        __syncthreads();
        const int k0 = kt * FT;
#pragma unroll
        for (int it = 0; it < 4; it++) {
            int id  = tid + it * 256;
            int row = id >> 4;
            int c4  = id & 15;
            float4 kv = *(const float4*)(Kg + (size_t)(k0 + row) * HDIM + c4 * 4);
            Kt[(c4 * 4 + 0) * FPAD + row] = kv.x;
            Kt[(c4 * 4 + 1) * FPAD + row] = kv.y;
            Kt[(c4 * 4 + 2) * FPAD + row] = kv.z;
            Kt[(c4 * 4 + 3) * FPAD + row] = kv.w;
            float4 vv = *(const float4*)(Vg + (size_t)(k0 + row) * HDIM + c4 * 4);
            *(float4*)(&Vs[row * FPAD + c4 * 4]) = vv;
        }
        __syncthreads();

        float s[4][4];
#pragma unroll
        for (int i = 0; i < 4; i++)
#pragma unroll
            for (int j = 0; j < 4; j++) s[i][j] = 0.0f;

        for (int kk = 0; kk < FT; kk++) {
            float a[4], b[4];
#pragma unroll
            for (int i = 0; i < 4; i++) a[i] = Qt[kk * FPAD + ty * 4 + i];
#pragma unroll
            for (int j = 0; j < 4; j++) b[j] = Kt[kk * FPAD + tx * 4 + j];
#pragma unroll
            for (int i = 0; i < 4; i++)
#pragma unroll
                for (int j = 0; j < 4; j++) s[i][j] += a[i] * b[j];
        }

        const bool diag = (kt == qt);
#pragma unroll
        for (int i = 0; i < 4; i++) {
            int qidx = q0 + ty * 4 + i;
#pragma unroll
            for (int j = 0; j < 4; j++) {
                s[i][j] *= scale;
                if (diag && (k0 + tx * 4 + j) > qidx) s[i][j] = -1e30f;
            }
        }

#pragma unroll
        for (int i = 0; i < 4; i++) {
            float mx = fmaxf(fmaxf(s[i][0], s[i][1]), fmaxf(s[i][2], s[i][3]));
#pragma unroll
            for (int off = 8; off >= 1; off >>= 1)
                mx = fmaxf(mx, __shfl_xor_sync(0xffffffffu, mx, off));
            float m_new = fmaxf(m_r[i], mx);
            float alpha = __expf(m_r[i] - m_new);
            float sum = 0.0f;
#pragma unroll
            for (int j = 0; j < 4; j++) {
                float p = __expf(s[i][j] - m_new);
                s[i][j] = p;
                sum += p;
            }
#pragma unroll
            for (int off = 8; off >= 1; off >>= 1)
                sum += __shfl_xor_sync(0xffffffffu, sum, off);
            l_r[i] = l_r[i] * alpha + sum;
            m_r[i] = m_new;
#pragma unroll
            for (int j = 0; j < 4; j++) acc[i][j] *= alpha;
        }

#pragma unroll
        for (int i = 0; i < 4; i++)
#pragma unroll
            for (int j = 0; j < 4; j++)
                Pt[(tx * 4 + j) * FPAD + ty * 4 + i] = s[i][j];
        __syncthreads();

        for (int kk = 0; kk < FT; kk++) {
            float p[4], v[4];
#pragma unroll
            for (int i = 0; i < 4; i++) p[i] = Pt[kk * FPAD + ty * 4 + i];
#pragma unroll
            for (int j = 0; j < 4; j++) v[j] = Vs[kk * FPAD + tx * 4 + j];
#pragma unroll
            for (int i = 0; i < 4; i++)
#pragma unroll
                for (int j = 0; j < 4; j++) acc[i][j] += p[i] * v[j];
        }
    }

    const int b = bh >> 4, h = bh & 15;
#pragma unroll
    for (int i = 0; i < 4; i++) {
        float inv = 1.0f / l_r[i];
        int q = q0 + ty * 4 + i;
#pragma unroll
        for (int j = 0; j < 4; j++) {
            g_CTX[((size_t)(b * S_LEN + q)) * EMB + h * HDIM + tx * 4 + j] =
                cvt_tf32(acc[i][j] * inv);
        }
    }
}

// ---------------------------------------------------------------------------
extern "C" void kernel_launch(void* const* d_in, const int* in_sizes, int n_in,
                              void* d_out, int out_size)
{
    const float* x      = (const float*)d_in[0];
    const float* w_attn = (const float*)d_in[1];
    const float* b_attn = (const float*)d_in[2];
    const float* w_proj = (const float*)d_in[3];
    const float* b_proj = (const float*)d_in[4];
    float* out = (float*)d_out;

    cudaFuncSetAttribute(gemm_tc<0>, cudaFuncAttributeMaxDynamicSharedMemorySize, GSMEM_BYTES);
    cudaFuncSetAttribute(gemm_tc<1>, cudaFuncAttributeMaxDynamicSharedMemorySize, GSMEM_BYTES);
    int fsmem = 4 * FT * FPAD * (int)sizeof(float);
    cudaFuncSetAttribute(flash_kernel, cudaFuncAttributeMaxDynamicSharedMemorySize, fsmem);

    // 0) pre-round x, transpose+round weights
    round_x<<<ROWS * EMB / 4 / 256, 256>>>(x);
    transpose_tf32<0><<<dim3(3 * EMB / 32, EMB / 32), dim3(32, 8)>>>(w_attn, EMB, 3 * EMB);
    transpose_tf32<1><<<dim3(EMB / 32, EMB / 32),     dim3(32, 8)>>>(w_proj, EMB, EMB);

    // 1) QKV GEMM (tf32 mma.sync) + scatter to g_Q/g_K/g_V
    gemm_tc<0><<<dim3(3 * EMB / TN, ROWS / TM), 128, GSMEM_BYTES>>>(b_attn, nullptr);

    // 2) causal flash attention (fp32) -> g_CTX (tf32-rounded)
    flash_kernel<<<dim3(S_LEN / FT, B_SZ * NHEAD), 256, fsmem>>>();

    // 3) projection GEMM (tf32 mma.sync) -> out
    gemm_tc<1><<<dim3(EMB / TN, ROWS / TM), 128, GSMEM_BYTES>>>(b_proj, out);
}

// round 5
// speedup vs baseline: 2.2984x; 1.6382x over previous
#include <cuda_runtime.h>
#include <cuda_bf16.h>
#include <cstdint>
#include <math.h>

// Problem constants
#define B_SZ   2
#define S_LEN  2048
#define EMB    1024
#define NHEAD  16
#define HDIM   64
#define ROWS   (B_SZ * S_LEN)          // 4096

// Scratch (device globals -> no allocation)
__device__ float g_Q[B_SZ * NHEAD * S_LEN * HDIM];
__device__ float g_K[B_SZ * NHEAD * S_LEN * HDIM];
__device__ float g_V[B_SZ * NHEAD * S_LEN * HDIM];
__device__ float g_CTX[ROWS * EMB];
__device__ float g_Xr[ROWS * EMB];       // tf32-rounded x
__device__ float g_WaT[3 * EMB * EMB];   // w_attn^T, tf32-rounded
__device__ float g_WpT[EMB * EMB];       // w_proj^T, tf32-rounded

// ---------------------------------------------------------------------------
// Helpers
// ---------------------------------------------------------------------------
__device__ __forceinline__ uint32_t smem_u32(const void* p) {
    uint32_t a;
    asm("{ .reg .u64 t; cvta.to.shared.u64 t, %1; cvt.u32.u64 %0, t; }"
        : "=r"(a) : "l"(p));
    return a;
}
__device__ __forceinline__ float cvt_tf32(float v) {
    float o;
    asm("cvt.rna.tf32.f32 %0, %1;" : "=f"(o) : "f"(v));
    return o;
}
__device__ __forceinline__ void cp16(uint32_t smaddr, const void* gaddr) {
    asm volatile("cp.async.cg.shared.global [%0], [%1], 16;"
                 :: "r"(smaddr), "l"(gaddr) : "memory");
}
__device__ __forceinline__ void mma_tf32(float& d0, float& d1, float& d2, float& d3,
                                         float a0, float a1, float a2, float a3,
                                         float b0, float b1) {
    asm volatile(
        "mma.sync.aligned.m16n8k8.row.col.f32.tf32.tf32.f32 "
        "{%0,%1,%2,%3},{%4,%5,%6,%7},{%8,%9},{%0,%1,%2,%3};"
        : "+f"(d0), "+f"(d1), "+f"(d2), "+f"(d3)
        : "r"(__float_as_uint(a0)), "r"(__float_as_uint(a1)),
          "r"(__float_as_uint(a2)), "r"(__float_as_uint(a3)),
          "r"(__float_as_uint(b0)), "r"(__float_as_uint(b1)));
}

// ---------------------------------------------------------------------------
// Pre-round x to tf32 (unbiased rna) into g_Xr
// ---------------------------------------------------------------------------
__global__ void round_x(const float* __restrict__ x)
{
    int i = (blockIdx.x * 256 + threadIdx.x) * 4;
    float4 v = *(const float4*)(x + i);
    v.x = cvt_tf32(v.x); v.y = cvt_tf32(v.y);
    v.z = cvt_tf32(v.z); v.w = cvt_tf32(v.w);
    *(float4*)(g_Xr + i) = v;
}

// ---------------------------------------------------------------------------
// Weight transpose with tf32 pre-rounding: src[K][N] -> dst[N][K]
// ---------------------------------------------------------------------------
template <int W>
__global__ void transpose_tf32(const float* __restrict__ src, int K, int N)
{
    __shared__ float t[32][33];
    float* dst = (W == 0) ? g_WaT : g_WpT;
    const int x = threadIdx.x, y = threadIdx.y;
    const int n0 = blockIdx.x * 32, k0 = blockIdx.y * 32;
#pragma unroll
    for (int i = 0; i < 4; i++) {
        float v = src[(size_t)(k0 + y + i * 8) * N + n0 + x];
        t[y + i * 8][x] = cvt_tf32(v);
    }
    __syncthreads();
#pragma unroll
    for (int i = 0; i < 4; i++)
        dst[(size_t)(n0 + y + i * 8) * K + k0 + x] = t[x][y + i * 8];
}

// ---------------------------------------------------------------------------
// tf32 mma.sync GEMM: D[M,N] = A[M,1024] @ BT[N,1024]^T + bias[N]
// CTA 128x128, 8 warps (2x4 grid, 64x32 warp tiles), K-chunk 32, double buffer.
// MODE 0: A = g_Xr, BT = g_WaT, scatter (tf32-rounded) to g_Q/g_K/g_V
// MODE 1: A = g_CTX, BT = g_WpT, write Cout row-major (no rounding: final out)
// ---------------------------------------------------------------------------
#define TM 128
#define TN 128
#define TK 32
#define PAD 36
#define ABUF (TM * PAD)                 // 4608 floats
#define NSTAGE (EMB / TK)               // 32
#define GSMEM_BYTES (2 * 2 * ABUF * 4)  // 73728

template <int MODE>
__global__ void __launch_bounds__(256)
gemm_tc(const float* __restrict__ bias, float* __restrict__ Cout)
{
    extern __shared__ float smf[];
    const int tid  = threadIdx.x;
    const int wid  = tid >> 5;
    const int lane = tid & 31;
    const int gid  = lane >> 2;          // 0..7
    const int tig  = lane & 3;           // 0..3
    const int warp_m = (wid >> 2) * 64;  // 2 warp-rows
    const int warp_n = (wid & 3) * 32;   // 4 warp-cols
    const int m0 = blockIdx.y * TM;
    const int n0 = blockIdx.x * TN;

    const float* A  = (MODE == 1) ? g_CTX : g_Xr;
    const float* BT = (MODE == 1) ? g_WpT : g_WaT;

    float acc[4][4][4];
#pragma unroll
    for (int mt = 0; mt < 4; mt++)
#pragma unroll
        for (int nt = 0; nt < 4; nt++)
#pragma unroll
            for (int r = 0; r < 4; r++) acc[mt][nt][r] = 0.0f;

#define ISSUE(s_)                                                              \
    {                                                                          \
        float* dA = smf + ((s_) & 1) * (2 * ABUF);                             \
        const int rr  = tid & 127;                                             \
        const float* g = (tid < 128)                                           \
            ? (A  + (size_t)(m0 + rr) * EMB + (s_) * TK)                       \
            : (BT + (size_t)(n0 + rr) * EMB + (s_) * TK);                      \
        uint32_t sa = smem_u32(dA + ((tid < 128) ? 0 : ABUF) + rr * PAD);      \
        _Pragma("unroll")                                                      \
        for (int c = 0; c < 8; c++) cp16(sa + c * 16, g + c * 4);              \
        asm volatile("cp.async.commit_group;" ::: "memory");                   \
    }

    ISSUE(0);
    for (int s = 0; s < NSTAGE; s++) {
        if (s + 1 < NSTAGE) {
            ISSUE(s + 1);
            asm volatile("cp.async.wait_group 1;" ::: "memory");
        } else {
            asm volatile("cp.async.wait_group 0;" ::: "memory");
        }
        __syncthreads();

        const float* As = smf + (s & 1) * (2 * ABUF);
        const float* Bs = As + ABUF;
#pragma unroll
        for (int kk = 0; kk < 4; kk++) {
            float af[4][4], bf[4][2];
            const int kb = kk * 8 + tig;
#pragma unroll
            for (int mt = 0; mt < 4; mt++) {
                const int m = warp_m + mt * 16 + gid;
                af[mt][0] = As[m * PAD + kb];
                af[mt][1] = As[(m + 8) * PAD + kb];
                af[mt][2] = As[m * PAD + kb + 4];
                af[mt][3] = As[(m + 8) * PAD + kb + 4];
            }
#pragma unroll
            for (int nt = 0; nt < 4; nt++) {
                const int n = warp_n + nt * 8 + gid;
                bf[nt][0] = Bs[n * PAD + kb];
                bf[nt][1] = Bs[n * PAD + kb + 4];
            }
#pragma unroll
            for (int mt = 0; mt < 4; mt++)
#pragma unroll
                for (int nt = 0; nt < 4; nt++)
                    mma_tf32(acc[mt][nt][0], acc[mt][nt][1],
                             acc[mt][nt][2], acc[mt][nt][3],
                             af[mt][0], af[mt][1], af[mt][2], af[mt][3],
                             bf[nt][0], bf[nt][1]);
        }
        __syncthreads();
    }
#undef ISSUE

#pragma unroll
    for (int mt = 0; mt < 4; mt++) {
        const int r0 = m0 + warp_m + mt * 16 + gid;
        const int r1 = r0 + 8;
#pragma unroll
        for (int nt = 0; nt < 4; nt++) {
            const int nb = n0 + warp_n + nt * 8;
            const int c  = nb + tig * 2;
            const float2 bv = *(const float2*)(bias + c);
            float2 o0, o1;
            o0.x = acc[mt][nt][0] + bv.x;
            o0.y = acc[mt][nt][1] + bv.y;
            o1.x = acc[mt][nt][2] + bv.x;
            o1.y = acc[mt][nt][3] + bv.y;
            if (MODE == 1) {
                *(float2*)(Cout + (size_t)r0 * EMB + c) = o0;
                *(float2*)(Cout + (size_t)r1 * EMB + c) = o1;
            } else {
                o0.x = cvt_tf32(o0.x); o0.y = cvt_tf32(o0.y);
                o1.x = cvt_tf32(o1.x); o1.y = cvt_tf32(o1.y);
                const int which = nb >> 10;
                const int e  = nb & 1023;
                const int h  = e >> 6;
                const int dd = (e & 63) + tig * 2;
                float* dst = (which == 0) ? g_Q : (which == 1) ? g_K : g_V;
                const int b0i = r0 >> 11, s0i = r0 & 2047;
                const int b1i = r1 >> 11, s1i = r1 & 2047;
                *(float2*)(dst + (((size_t)(b0i * NHEAD + h)) * S_LEN + s0i) * HDIM + dd) = o0;
                *(float2*)(dst + (((size_t)(b1i * NHEAD + h)) * S_LEN + s1i) * HDIM + dd) = o1;
            }
        }
    }
}

// ---------------------------------------------------------------------------
// Flash attention (causal) with tf32 mma.sync.
// CTA: 256 thr / 8 warps; q-tile 128 (16 rows per warp); k-tile 64; D=64.
// Q A-frags in regs; K,V in smem; P acc->A-frag via intra-quad shuffles.
// ---------------------------------------------------------------------------
#define QPAD 68
#define KPAD 68
#define VPAD 72
#define FLASH_SMEM ((128 * QPAD + 64 * KPAD + 64 * VPAD) * 4)   // 70656

__global__ void __launch_bounds__(256)
flash_kernel()
{
    extern __shared__ float sm[];
    float* Qs = sm;                      // [128][68]
    float* Ks = Qs + 128 * QPAD;         // [64][68]
    float* Vs = Ks + 64 * KPAD;          // [64][72]

    const int tid  = threadIdx.x;
    const int wid  = tid >> 5;
    const int lane = tid & 31;
    const int gid  = lane >> 2;
    const int tig  = lane & 3;
    const int qt   = blockIdx.x;
    const int bh   = blockIdx.y;
    const int q0   = qt * 128;

    const float* Qg = g_Q + (size_t)bh * S_LEN * HDIM;
    const float* Kg = g_K + (size_t)bh * S_LEN * HDIM;
    const float* Vg = g_V + (size_t)bh * S_LEN * HDIM;

    // Load Q tile 128x64 to smem
#pragma unroll
    for (int it = 0; it < 8; it++) {
        int id  = tid + it * 256;
        int row = id >> 4;
        int c4  = id & 15;
        float4 v = *(const float4*)(Qg + (size_t)(q0 + row) * HDIM + c4 * 4);
        *(float4*)(&Qs[row * QPAD + c4 * 4]) = v;
    }
    __syncthreads();

    // Q A-fragments (row group = wid*16)
    const int qrow = wid * 16 + gid;
    float qa[8][4];
#pragma unroll
    for (int kk = 0; kk < 8; kk++) {
        qa[kk][0] = Qs[qrow * QPAD + kk * 8 + tig];
        qa[kk][1] = Qs[(qrow + 8) * QPAD + kk * 8 + tig];
        qa[kk][2] = Qs[qrow * QPAD + kk * 8 + tig + 4];
        qa[kk][3] = Qs[(qrow + 8) * QPAD + kk * 8 + tig + 4];
    }

    float m0v = -1e30f, m1v = -1e30f, l0 = 0.0f, l1 = 0.0f;
    float o[8][4];
#pragma unroll
    for (int nt = 0; nt < 8; nt++)
#pragma unroll
        for (int r = 0; r < 4; r++) o[nt][r] = 0.0f;

    const int r0g = q0 + wid * 16 + gid;
    const int nkt = 2 * (qt + 1);

    for (int kt = 0; kt < nkt; kt++) {
        const int k0 = kt * 64;
        __syncthreads();   // prev PV reads done before overwrite
#pragma unroll
        for (int it = 0; it < 4; it++) {
            int id  = tid + it * 256;
            int row = id >> 4;
            int c4  = id & 15;
            *(float4*)(&Ks[row * KPAD + c4 * 4]) =
                *(const float4*)(Kg + (size_t)(k0 + row) * HDIM + c4 * 4);
            *(float4*)(&Vs[row * VPAD + c4 * 4]) =
                *(const float4*)(Vg + (size_t)(k0 + row) * HDIM + c4 * 4);
        }
        __syncthreads();

        // S = Q K^T
        float s[8][4];
#pragma unroll
        for (int nt = 0; nt < 8; nt++)
#pragma unroll
            for (int r = 0; r < 4; r++) s[nt][r] = 0.0f;

#pragma unroll
        for (int kk = 0; kk < 8; kk++) {
            const int kb = kk * 8 + tig;
#pragma unroll
            for (int nt = 0; nt < 8; nt++) {
                const int key = nt * 8 + gid;
                float b0 = Ks[key * KPAD + kb];
                float b1 = Ks[key * KPAD + kb + 4];
                mma_tf32(s[nt][0], s[nt][1], s[nt][2], s[nt][3],
                         qa[kk][0], qa[kk][1], qa[kk][2], qa[kk][3], b0, b1);
            }
        }

        // scale + causal mask
        const bool domask = (k0 + 63) > r0g;
#pragma unroll
        for (int nt = 0; nt < 8; nt++) {
            const int c0 = k0 + nt * 8 + tig * 2;
            s[nt][0] *= 0.125f; s[nt][1] *= 0.125f;
            s[nt][2] *= 0.125f; s[nt][3] *= 0.125f;
            if (domask) {
                if (c0 > r0g)         s[nt][0] = -1e30f;
                if (c0 + 1 > r0g)     s[nt][1] = -1e30f;
                if (c0 > r0g + 8)     s[nt][2] = -1e30f;
                if (c0 + 1 > r0g + 8) s[nt][3] = -1e30f;
            }
        }

        // online softmax
        float mx0 = -1e30f, mx1 = -1e30f;
#pragma unroll
        for (int nt = 0; nt < 8; nt++) {
            mx0 = fmaxf(mx0, fmaxf(s[nt][0], s[nt][1]));
            mx1 = fmaxf(mx1, fmaxf(s[nt][2], s[nt][3]));
        }
        mx0 = fmaxf(mx0, __shfl_xor_sync(0xffffffffu, mx0, 1));
        mx0 = fmaxf(mx0, __shfl_xor_sync(0xffffffffu, mx0, 2));
        mx1 = fmaxf(mx1, __shfl_xor_sync(0xffffffffu, mx1, 1));
        mx1 = fmaxf(mx1, __shfl_xor_sync(0xffffffffu, mx1, 2));

        const float mn0 = fmaxf(m0v, mx0);
        const float mn1 = fmaxf(m1v, mx1);
        const float al0 = __expf(m0v - mn0);
        const float al1 = __expf(m1v - mn1);
        m0v = mn0; m1v = mn1;

        float sum0 = 0.0f, sum1 = 0.0f;
#pragma unroll
        for (int nt = 0; nt < 8; nt++) {
            s[nt][0] = cvt_tf32(__expf(s[nt][0] - mn0));
            s[nt][1] = cvt_tf32(__expf(s[nt][1] - mn0));
            s[nt][2] = cvt_tf32(__expf(s[nt][2] - mn1));
            s[nt][3] = cvt_tf32(__expf(s[nt][3] - mn1));
            sum0 += s[nt][0] + s[nt][1];
            sum1 += s[nt][2] + s[nt][3];
        }
        sum0 += __shfl_xor_sync(0xffffffffu, sum0, 1);
        sum0 += __shfl_xor_sync(0xffffffffu, sum0, 2);
        sum1 += __shfl_xor_sync(0xffffffffu, sum1, 1);
        sum1 += __shfl_xor_sync(0xffffffffu, sum1, 2);
        l0 = l0 * al0 + sum0;
        l1 = l1 * al1 + sum1;

#pragma unroll
        for (int nt = 0; nt < 8; nt++) {
            o[nt][0] *= al0; o[nt][1] *= al0;
            o[nt][2] *= al1; o[nt][3] *= al1;
        }

        // O += P V  (P acc-layout -> A-frag via intra-quad shuffles)
        const int base = lane & ~3;
        const int srcA = base + (tig >> 1);
        const int srcB = srcA + 2;
        const bool odd = (tig & 1);
#pragma unroll
        for (int kc = 0; kc < 8; kc++) {
            float u0 = __shfl_sync(0xffffffffu, s[kc][0], srcA);
            float u1 = __shfl_sync(0xffffffffu, s[kc][1], srcA);
            float a0 = odd ? u1 : u0;
            float v0 = __shfl_sync(0xffffffffu, s[kc][0], srcB);
            float v1 = __shfl_sync(0xffffffffu, s[kc][1], srcB);
            float a2 = odd ? v1 : v0;
            float w0 = __shfl_sync(0xffffffffu, s[kc][2], srcA);
            float w1 = __shfl_sync(0xffffffffu, s[kc][3], srcA);
            float a1 = odd ? w1 : w0;
            float x0 = __shfl_sync(0xffffffffu, s[kc][2], srcB);
            float x1 = __shfl_sync(0xffffffffu, s[kc][3], srcB);
            float a3 = odd ? x1 : x0;
#pragma unroll
            for (int nt = 0; nt < 8; nt++) {
                float b0 = Vs[(kc * 8 + tig) * VPAD + nt * 8 + gid];
                float b1 = Vs[(kc * 8 + tig + 4) * VPAD + nt * 8 + gid];
                mma_tf32(o[nt][0], o[nt][1], o[nt][2], o[nt][3],
                         a0, a1, a2, a3, b0, b1);
            }
        }
    }

    // write ctx (tf32-rounded: feeds tf32 proj GEMM)
    const int b = bh >> 4, h = bh & 15;
    const float inv0 = 1.0f / l0;
    const float inv1 = 1.0f / l1;
    const int r1g = r0g + 8;
#pragma unroll
    for (int nt = 0; nt < 8; nt++) {
        const int col = h * HDIM + nt * 8 + tig * 2;
        float2 o0, o1;
        o0.x = cvt_tf32(o[nt][0] * inv0);
        o0.y = cvt_tf32(o[nt][1] * inv0);
        o1.x = cvt_tf32(o[nt][2] * inv1);
        o1.y = cvt_tf32(o[nt][3] * inv1);
        *(float2*)(g_CTX + ((size_t)(b * S_LEN + r0g)) * EMB + col) = o0;
        *(float2*)(g_CTX + ((size_t)(b * S_LEN + r1g)) * EMB + col) = o1;
    }
}

// ---------------------------------------------------------------------------
extern "C" void kernel_launch(void* const* d_in, const int* in_sizes, int n_in,
                              void* d_out, int out_size)
{
    const float* x      = (const float*)d_in[0];
    const float* w_attn = (const float*)d_in[1];
    const float* b_attn = (const float*)d_in[2];
    const float* w_proj = (const float*)d_in[3];
    const float* b_proj = (const float*)d_in[4];
    float* out = (float*)d_out;

    cudaFuncSetAttribute(gemm_tc<0>, cudaFuncAttributeMaxDynamicSharedMemorySize, GSMEM_BYTES);
    cudaFuncSetAttribute(gemm_tc<1>, cudaFuncAttributeMaxDynamicSharedMemorySize, GSMEM_BYTES);
    cudaFuncSetAttribute(flash_kernel, cudaFuncAttributeMaxDynamicSharedMemorySize, FLASH_SMEM);

    // 0) pre-round x, transpose+round weights
    round_x<<<ROWS * EMB / 4 / 256, 256>>>(x);
    transpose_tf32<0><<<dim3(3 * EMB / 32, EMB / 32), dim3(32, 8)>>>(w_attn, EMB, 3 * EMB);
    transpose_tf32<1><<<dim3(EMB / 32, EMB / 32),     dim3(32, 8)>>>(w_proj, EMB, EMB);

    // 1) QKV GEMM (tf32 mma.sync) -> g_Q/g_K/g_V (tf32-rounded)
    gemm_tc<0><<<dim3(3 * EMB / TN, ROWS / TM), 256, GSMEM_BYTES>>>(b_attn, nullptr);

    // 2) causal flash attention (tf32 mma.sync) -> g_CTX
    flash_kernel<<<dim3(S_LEN / 128, B_SZ * NHEAD), 256, FLASH_SMEM>>>();

    // 3) projection GEMM (tf32 mma.sync) -> out
    gemm_tc<1><<<dim3(EMB / TN, ROWS / TM), 256, GSMEM_BYTES>>>(b_proj, out);
}

// round 6
// speedup vs baseline: 2.4271x; 1.0560x over previous
#include <cuda_runtime.h>
#include <cuda_bf16.h>
#include <cstdint>
#include <math.h>

// Problem constants
#define B_SZ   2
#define S_LEN  2048
#define EMB    1024
#define NHEAD  16
#define HDIM   64
#define ROWS   (B_SZ * S_LEN)          // 4096

// Scratch (device globals -> no allocation)
__device__ float g_Q[B_SZ * NHEAD * S_LEN * HDIM];
__device__ float g_K[B_SZ * NHEAD * S_LEN * HDIM];
__device__ float g_V[B_SZ * NHEAD * S_LEN * HDIM];
__device__ float g_CTX[ROWS * EMB];
__device__ float g_Xr[ROWS * EMB];       // tf32-rounded x
__device__ float g_WaT[3 * EMB * EMB];   // w_attn^T, tf32-rounded
__device__ float g_WpT[EMB * EMB];       // w_proj^T, tf32-rounded

// ---------------------------------------------------------------------------
// Helpers
// ---------------------------------------------------------------------------
__device__ __forceinline__ uint32_t smem_u32(const void* p) {
    uint32_t a;
    asm("{ .reg .u64 t; cvta.to.shared.u64 t, %1; cvt.u32.u64 %0, t; }"
        : "=r"(a) : "l"(p));
    return a;
}
__device__ __forceinline__ float cvt_tf32(float v) {
    float o;
    asm("cvt.rna.tf32.f32 %0, %1;" : "=f"(o) : "f"(v));
    return o;
}
__device__ __forceinline__ void cp16(uint32_t smaddr, const void* gaddr) {
    asm volatile("cp.async.cg.shared.global [%0], [%1], 16;"
                 :: "r"(smaddr), "l"(gaddr) : "memory");
}
__device__ __forceinline__ void mma_tf32(float& d0, float& d1, float& d2, float& d3,
                                         float a0, float a1, float a2, float a3,
                                         float b0, float b1) {
    asm volatile(
        "mma.sync.aligned.m16n8k8.row.col.f32.tf32.tf32.f32 "
        "{%0,%1,%2,%3},{%4,%5,%6,%7},{%8,%9},{%0,%1,%2,%3};"
        : "+f"(d0), "+f"(d1), "+f"(d2), "+f"(d3)
        : "r"(__float_as_uint(a0)), "r"(__float_as_uint(a1)),
          "r"(__float_as_uint(a2)), "r"(__float_as_uint(a3)),
          "r"(__float_as_uint(b0)), "r"(__float_as_uint(b1)));
}

// ---------------------------------------------------------------------------
// Pre-round x to tf32 (unbiased rna) into g_Xr
// ---------------------------------------------------------------------------
__global__ void round_x(const float* __restrict__ x)
{
    int i = (blockIdx.x * 256 + threadIdx.x) * 4;
    float4 v = *(const float4*)(x + i);
    v.x = cvt_tf32(v.x); v.y = cvt_tf32(v.y);
    v.z = cvt_tf32(v.z); v.w = cvt_tf32(v.w);
    *(float4*)(g_Xr + i) = v;
}

// ---------------------------------------------------------------------------
// Weight transpose with tf32 pre-rounding: src[K][N] -> dst[N][K]
// ---------------------------------------------------------------------------
template <int W>
__global__ void transpose_tf32(const float* __restrict__ src, int K, int N)
{
    __shared__ float t[32][33];
    float* dst = (W == 0) ? g_WaT : g_WpT;
    const int x = threadIdx.x, y = threadIdx.y;
    const int n0 = blockIdx.x * 32, k0 = blockIdx.y * 32;
#pragma unroll
    for (int i = 0; i < 4; i++) {
        float v = src[(size_t)(k0 + y + i * 8) * N + n0 + x];
        t[y + i * 8][x] = cvt_tf32(v);
    }
    __syncthreads();
#pragma unroll
    for (int i = 0; i < 4; i++)
        dst[(size_t)(n0 + y + i * 8) * K + k0 + x] = t[x][y + i * 8];
}

// ---------------------------------------------------------------------------
// tf32 mma.sync GEMM: D[M,N] = A[M,1024] @ BT[N,1024]^T + bias[N]
// CTA 128x128, 8 warps (2x4 grid, 64x32 warp tiles).
// 3-stage cp.async pipeline, ONE __syncthreads per K-stage:
//   iter s: issue(s+2) -> compute(s) -> wait_group 1 -> barrier
// MODE 0: A = g_Xr, BT = g_WaT, scatter (tf32-rounded) to g_Q/g_K/g_V
// MODE 1: A = g_CTX, BT = g_WpT, write Cout row-major
// ---------------------------------------------------------------------------
#define TM 128
#define TN 128
#define TK 32
#define PAD 36
#define ABUF (TM * PAD)                 // 4608 floats (A or B tile)
#define STG_F (2 * ABUF)                // floats per stage (A+B)
#define NSTAGE (EMB / TK)               // 32
#define SPIPE 3
#define GSMEM_BYTES (SPIPE * STG_F * 4) // 110592

template <int MODE>
__global__ void __launch_bounds__(256, 2)
gemm_tc(const float* __restrict__ bias, float* __restrict__ Cout)
{
    extern __shared__ float smf[];
    const int tid  = threadIdx.x;
    const int wid  = tid >> 5;
    const int lane = tid & 31;
    const int gid  = lane >> 2;          // 0..7
    const int tig  = lane & 3;           // 0..3
    const int warp_m = (wid >> 2) * 64;  // 2 warp-rows
    const int warp_n = (wid & 3) * 32;   // 4 warp-cols
    const int m0 = blockIdx.y * TM;
    const int n0 = blockIdx.x * TN;

    const float* A  = (MODE == 1) ? g_CTX : g_Xr;
    const float* BT = (MODE == 1) ? g_WpT : g_WaT;

    float acc[4][4][4];
#pragma unroll
    for (int mt = 0; mt < 4; mt++)
#pragma unroll
        for (int nt = 0; nt < 4; nt++)
#pragma unroll
            for (int r = 0; r < 4; r++) acc[mt][nt][r] = 0.0f;

    // per-thread load slot (fixed): first 128 threads load A rows, rest B rows
    const int rr = tid & 127;
    const float* gsrc = (tid < 128)
        ? (A  + (size_t)(m0 + rr) * EMB)
        : (BT + (size_t)(n0 + rr) * EMB);
    const uint32_t sbase = smem_u32(smf + ((tid < 128) ? 0 : ABUF) + rr * PAD);

#define ISSUE(s_)                                                              \
    {                                                                          \
        uint32_t sa = sbase + (uint32_t)(((s_) % SPIPE) * STG_F * 4);          \
        const float* g = gsrc + (s_) * TK;                                     \
        _Pragma("unroll")                                                      \
        for (int c = 0; c < 8; c++) cp16(sa + c * 16, g + c * 4);              \
    }

    // prologue: stages 0,1 in flight
    ISSUE(0);
    asm volatile("cp.async.commit_group;" ::: "memory");
    ISSUE(1);
    asm volatile("cp.async.commit_group;" ::: "memory");
    asm volatile("cp.async.wait_group 1;" ::: "memory");
    __syncthreads();

    for (int s = 0; s < NSTAGE; s++) {
        // issue stage s+2 (slot (s-1)%3: all warps left it at iter-s barrier)
        if (s + 2 < NSTAGE) ISSUE(s + 2);
        asm volatile("cp.async.commit_group;" ::: "memory");

        const float* As = smf + (s % SPIPE) * STG_F;
        const float* Bs = As + ABUF;
#pragma unroll
        for (int kk = 0; kk < 4; kk++) {
            float af[4][4], bf[4][2];
            const int kb = kk * 8 + tig;
#pragma unroll
            for (int mt = 0; mt < 4; mt++) {
                const int m = warp_m + mt * 16 + gid;
                af[mt][0] = As[m * PAD + kb];
                af[mt][1] = As[(m + 8) * PAD + kb];
                af[mt][2] = As[m * PAD + kb + 4];
                af[mt][3] = As[(m + 8) * PAD + kb + 4];
            }
#pragma unroll
            for (int nt = 0; nt < 4; nt++) {
                const int n = warp_n + nt * 8 + gid;
                bf[nt][0] = Bs[n * PAD + kb];
                bf[nt][1] = Bs[n * PAD + kb + 4];
            }
#pragma unroll
            for (int mt = 0; mt < 4; mt++)
#pragma unroll
                for (int nt = 0; nt < 4; nt++)
                    mma_tf32(acc[mt][nt][0], acc[mt][nt][1],
                             acc[mt][nt][2], acc[mt][nt][3],
                             af[mt][0], af[mt][1], af[mt][2], af[mt][3],
                             bf[nt][0], bf[nt][1]);
        }
        // ensure stage s+1 arrived (2 groups pending -> keep newest only)
        asm volatile("cp.async.wait_group 1;" ::: "memory");
        __syncthreads();
    }
#undef ISSUE

#pragma unroll
    for (int mt = 0; mt < 4; mt++) {
        const int r0 = m0 + warp_m + mt * 16 + gid;
        const int r1 = r0 + 8;
#pragma unroll
        for (int nt = 0; nt < 4; nt++) {
            const int nb = n0 + warp_n + nt * 8;
            const int c  = nb + tig * 2;
            const float2 bv = *(const float2*)(bias + c);
            float2 o0, o1;
            o0.x = acc[mt][nt][0] + bv.x;
            o0.y = acc[mt][nt][1] + bv.y;
            o1.x = acc[mt][nt][2] + bv.x;
            o1.y = acc[mt][nt][3] + bv.y;
            if (MODE == 1) {
                *(float2*)(Cout + (size_t)r0 * EMB + c) = o0;
                *(float2*)(Cout + (size_t)r1 * EMB + c) = o1;
            } else {
                o0.x = cvt_tf32(o0.x); o0.y = cvt_tf32(o0.y);
                o1.x = cvt_tf32(o1.x); o1.y = cvt_tf32(o1.y);
                const int which = nb >> 10;
                const int e  = nb & 1023;
                const int h  = e >> 6;
                const int dd = (e & 63) + tig * 2;
                float* dst = (which == 0) ? g_Q : (which == 1) ? g_K : g_V;
                const int b0i = r0 >> 11, s0i = r0 & 2047;
                const int b1i = r1 >> 11, s1i = r1 & 2047;
                *(float2*)(dst + (((size_t)(b0i * NHEAD + h)) * S_LEN + s0i) * HDIM + dd) = o0;
                *(float2*)(dst + (((size_t)(b1i * NHEAD + h)) * S_LEN + s1i) * HDIM + dd) = o1;
            }
        }
    }
}

// ---------------------------------------------------------------------------
// Flash attention (causal) with tf32 mma.sync — unchanged from R5 (verified).
// ---------------------------------------------------------------------------
#define QPAD 68
#define KPAD 68
#define VPAD 72
#define FLASH_SMEM ((128 * QPAD + 64 * KPAD + 64 * VPAD) * 4)   // 70656

__global__ void __launch_bounds__(256)
flash_kernel()
{
    extern __shared__ float sm[];
    float* Qs = sm;                      // [128][68]
    float* Ks = Qs + 128 * QPAD;         // [64][68]
    float* Vs = Ks + 64 * KPAD;          // [64][72]

    const int tid  = threadIdx.x;
    const int wid  = tid >> 5;
    const int lane = tid & 31;
    const int gid  = lane >> 2;
    const int tig  = lane & 3;
    const int qt   = blockIdx.x;
    const int bh   = blockIdx.y;
    const int q0   = qt * 128;

    const float* Qg = g_Q + (size_t)bh * S_LEN * HDIM;
    const float* Kg = g_K + (size_t)bh * S_LEN * HDIM;
    const float* Vg = g_V + (size_t)bh * S_LEN * HDIM;

#pragma unroll
    for (int it = 0; it < 8; it++) {
        int id  = tid + it * 256;
        int row = id >> 4;
        int c4  = id & 15;
        float4 v = *(const float4*)(Qg + (size_t)(q0 + row) * HDIM + c4 * 4);
        *(float4*)(&Qs[row * QPAD + c4 * 4]) = v;
    }
    __syncthreads();

    const int qrow = wid * 16 + gid;
    float qa[8][4];
#pragma unroll
    for (int kk = 0; kk < 8; kk++) {
        qa[kk][0] = Qs[qrow * QPAD + kk * 8 + tig];
        qa[kk][1] = Qs[(qrow + 8) * QPAD + kk * 8 + tig];
        qa[kk][2] = Qs[qrow * QPAD + kk * 8 + tig + 4];
        qa[kk][3] = Qs[(qrow + 8) * QPAD + kk * 8 + tig + 4];
    }

    float m0v = -1e30f, m1v = -1e30f, l0 = 0.0f, l1 = 0.0f;
    float o[8][4];
#pragma unroll
    for (int nt = 0; nt < 8; nt++)
#pragma unroll
        for (int r = 0; r < 4; r++) o[nt][r] = 0.0f;

    const int r0g = q0 + wid * 16 + gid;
    const int nkt = 2 * (qt + 1);

    for (int kt = 0; kt < nkt; kt++) {
        const int k0 = kt * 64;
        __syncthreads();
#pragma unroll
        for (int it = 0; it < 4; it++) {
            int id  = tid + it * 256;
            int row = id >> 4;
            int c4  = id & 15;
            *(float4*)(&Ks[row * KPAD + c4 * 4]) =
                *(const float4*)(Kg + (size_t)(k0 + row) * HDIM + c4 * 4);
            *(float4*)(&Vs[row * VPAD + c4 * 4]) =
                *(const float4*)(Vg + (size_t)(k0 + row) * HDIM + c4 * 4);
        }
        __syncthreads();

        float s[8][4];
#pragma unroll
        for (int nt = 0; nt < 8; nt++)
#pragma unroll
            for (int r = 0; r < 4; r++) s[nt][r] = 0.0f;

#pragma unroll
        for (int kk = 0; kk < 8; kk++) {
            const int kb = kk * 8 + tig;
#pragma unroll
            for (int nt = 0; nt < 8; nt++) {
                const int key = nt * 8 + gid;
                float b0 = Ks[key * KPAD + kb];
                float b1 = Ks[key * KPAD + kb + 4];
                mma_tf32(s[nt][0], s[nt][1], s[nt][2], s[nt][3],
                         qa[kk][0], qa[kk][1], qa[kk][2], qa[kk][3], b0, b1);
            }
        }

        const bool domask = (k0 + 63) > r0g;
#pragma unroll
        for (int nt = 0; nt < 8; nt++) {
            const int c0 = k0 + nt * 8 + tig * 2;
            s[nt][0] *= 0.125f; s[nt][1] *= 0.125f;
            s[nt][2] *= 0.125f; s[nt][3] *= 0.125f;
            if (domask) {
                if (c0 > r0g)         s[nt][0] = -1e30f;
                if (c0 + 1 > r0g)     s[nt][1] = -1e30f;
                if (c0 > r0g + 8)     s[nt][2] = -1e30f;
                if (c0 + 1 > r0g + 8) s[nt][3] = -1e30f;
            }
        }

        float mx0 = -1e30f, mx1 = -1e30f;
#pragma unroll
        for (int nt = 0; nt < 8; nt++) {
            mx0 = fmaxf(mx0, fmaxf(s[nt][0], s[nt][1]));
            mx1 = fmaxf(mx1, fmaxf(s[nt][2], s[nt][3]));
        }
        mx0 = fmaxf(mx0, __shfl_xor_sync(0xffffffffu, mx0, 1));
        mx0 = fmaxf(mx0, __shfl_xor_sync(0xffffffffu, mx0, 2));
        mx1 = fmaxf(mx1, __shfl_xor_sync(0xffffffffu, mx1, 1));
        mx1 = fmaxf(mx1, __shfl_xor_sync(0xffffffffu, mx1, 2));

        const float mn0 = fmaxf(m0v, mx0);
        const float mn1 = fmaxf(m1v, mx1);
        const float al0 = __expf(m0v - mn0);
        const float al1 = __expf(m1v - mn1);
        m0v = mn0; m1v = mn1;

        float sum0 = 0.0f, sum1 = 0.0f;
#pragma unroll
        for (int nt = 0; nt < 8; nt++) {
            s[nt][0] = cvt_tf32(__expf(s[nt][0] - mn0));
            s[nt][1] = cvt_tf32(__expf(s[nt][1] - mn0));
            s[nt][2] = cvt_tf32(__expf(s[nt][2] - mn1));
            s[nt][3] = cvt_tf32(__expf(s[nt][3] - mn1));
            sum0 += s[nt][0] + s[nt][1];
            sum1 += s[nt][2] + s[nt][3];
        }
        sum0 += __shfl_xor_sync(0xffffffffu, sum0, 1);
        sum0 += __shfl_xor_sync(0xffffffffu, sum0, 2);
        sum1 += __shfl_xor_sync(0xffffffffu, sum1, 1);
        sum1 += __shfl_xor_sync(0xffffffffu, sum1, 2);
        l0 = l0 * al0 + sum0;
        l1 = l1 * al1 + sum1;

#pragma unroll
        for (int nt = 0; nt < 8; nt++) {
            o[nt][0] *= al0; o[nt][1] *= al0;
            o[nt][2] *= al1; o[nt][3] *= al1;
        }

        const int base = lane & ~3;
        const int srcA = base + (tig >> 1);
        const int srcB = srcA + 2;
        const bool odd = (tig & 1);
#pragma unroll
        for (int kc = 0; kc < 8; kc++) {
            float u0 = __shfl_sync(0xffffffffu, s[kc][0], srcA);
            float u1 = __shfl_sync(0xffffffffu, s[kc][1], srcA);
            float a0 = odd ? u1 : u0;
            float v0 = __shfl_sync(0xffffffffu, s[kc][0], srcB);
            float v1 = __shfl_sync(0xffffffffu, s[kc][1], srcB);
            float a2 = odd ? v1 : v0;
            float w0 = __shfl_sync(0xffffffffu, s[kc][2], srcA);
            float w1 = __shfl_sync(0xffffffffu, s[kc][3], srcA);
            float a1 = odd ? w1 : w0;
            float x0 = __shfl_sync(0xffffffffu, s[kc][2], srcB);
            float x1 = __shfl_sync(0xffffffffu, s[kc][3], srcB);
            float a3 = odd ? x1 : x0;
#pragma unroll
            for (int nt = 0; nt < 8; nt++) {
                float b0 = Vs[(kc * 8 + tig) * VPAD + nt * 8 + gid];
                float b1 = Vs[(kc * 8 + tig + 4) * VPAD + nt * 8 + gid];
                mma_tf32(o[nt][0], o[nt][1], o[nt][2], o[nt][3],
                         a0, a1, a2, a3, b0, b1);
            }
        }
    }

    const int b = bh >> 4, h = bh & 15;
    const float inv0 = 1.0f / l0;
    const float inv1 = 1.0f / l1;
    const int r1g = r0g + 8;
#pragma unroll
    for (int nt = 0; nt < 8; nt++) {
        const int col = h * HDIM + nt * 8 + tig * 2;
        float2 o0, o1;
        o0.x = cvt_tf32(o[nt][0] * inv0);
        o0.y = cvt_tf32(o[nt][1] * inv0);
        o1.x = cvt_tf32(o[nt][2] * inv1);
        o1.y = cvt_tf32(o[nt][3] * inv1);
        *(float2*)(g_CTX + ((size_t)(b * S_LEN + r0g)) * EMB + col) = o0;
        *(float2*)(g_CTX + ((size_t)(b * S_LEN + r1g)) * EMB + col) = o1;
    }
}

// ---------------------------------------------------------------------------
extern "C" void kernel_launch(void* const* d_in, const int* in_sizes, int n_in,
                              void* d_out, int out_size)
{
    const float* x      = (const float*)d_in[0];
    const float* w_attn = (const float*)d_in[1];
    const float* b_attn = (const float*)d_in[2];
    const float* w_proj = (const float*)d_in[3];
    const float* b_proj = (const float*)d_in[4];
    float* out = (float*)d_out;

    cudaFuncSetAttribute(gemm_tc<0>, cudaFuncAttributeMaxDynamicSharedMemorySize, GSMEM_BYTES);
    cudaFuncSetAttribute(gemm_tc<1>, cudaFuncAttributeMaxDynamicSharedMemorySize, GSMEM_BYTES);
    cudaFuncSetAttribute(flash_kernel, cudaFuncAttributeMaxDynamicSharedMemorySize, FLASH_SMEM);

    // 0) pre-round x, transpose+round weights
    round_x<<<ROWS * EMB / 4 / 256, 256>>>(x);
    transpose_tf32<0><<<dim3(3 * EMB / 32, EMB / 32), dim3(32, 8)>>>(w_attn, EMB, 3 * EMB);
    transpose_tf32<1><<<dim3(EMB / 32, EMB / 32),     dim3(32, 8)>>>(w_proj, EMB, EMB);

    // 1) QKV GEMM (tf32 mma.sync) -> g_Q/g_K/g_V (tf32-rounded)
    gemm_tc<0><<<dim3(3 * EMB / TN, ROWS / TM), 256, GSMEM_BYTES>>>(b_attn, nullptr);

    // 2) causal flash attention (tf32 mma.sync) -> g_CTX
    flash_kernel<<<dim3(S_LEN / 128, B_SZ * NHEAD), 256, FLASH_SMEM>>>();

    // 3) projection GEMM (tf32 mma.sync) -> out
    gemm_tc<1><<<dim3(EMB / TN, ROWS / TM), 256, GSMEM_BYTES>>>(b_proj, out);
}

// round 7
// speedup vs baseline: 2.5670x; 1.0577x over previous
#include <cuda_runtime.h>
#include <cuda_bf16.h>
#include <cstdint>
#include <math.h>

// Problem constants
#define B_SZ   2
#define S_LEN  2048
#define EMB    1024
#define NHEAD  16
#define HDIM   64
#define ROWS   (B_SZ * S_LEN)          // 4096

// Scratch (device globals -> no allocation)
// g_Xr, g_WaT, g_WpT, g_CTX use k-PERMUTED layout: within each 8-col k-group,
// logical col l is stored at position (l<4 ? 2l : 2l-7)  => order [0,4,1,5,2,6,3,7].
// This makes tf32 mma fragment pairs (k, k+4) contiguous (one float2).
__device__ float g_Q[B_SZ * NHEAD * S_LEN * HDIM];
__device__ float g_K[B_SZ * NHEAD * S_LEN * HDIM];
__device__ float g_V[B_SZ * NHEAD * S_LEN * HDIM];
__device__ float g_CTX[ROWS * EMB];
__device__ float g_Xr[ROWS * EMB];
__device__ float g_WaT[3 * EMB * EMB];
__device__ float g_WpT[EMB * EMB];

// ---------------------------------------------------------------------------
// Helpers
// ---------------------------------------------------------------------------
__device__ __forceinline__ uint32_t smem_u32(const void* p) {
    uint32_t a;
    asm("{ .reg .u64 t; cvta.to.shared.u64 t, %1; cvt.u32.u64 %0, t; }"
        : "=r"(a) : "l"(p));
    return a;
}
__device__ __forceinline__ float cvt_tf32(float v) {
    float o;
    asm("cvt.rna.tf32.f32 %0, %1;" : "=f"(o) : "f"(v));
    return o;
}
__device__ __forceinline__ void cp16(uint32_t smaddr, const void* gaddr) {
    asm volatile("cp.async.cg.shared.global [%0], [%1], 16;"
                 :: "r"(smaddr), "l"(gaddr) : "memory");
}
__device__ __forceinline__ void mma_tf32(float& d0, float& d1, float& d2, float& d3,
                                         float a0, float a1, float a2, float a3,
                                         float b0, float b1) {
    asm volatile(
        "mma.sync.aligned.m16n8k8.row.col.f32.tf32.tf32.f32 "
        "{%0,%1,%2,%3},{%4,%5,%6,%7},{%8,%9},{%0,%1,%2,%3};"
        : "+f"(d0), "+f"(d1), "+f"(d2), "+f"(d3)
        : "r"(__float_as_uint(a0)), "r"(__float_as_uint(a1)),
          "r"(__float_as_uint(a2)), "r"(__float_as_uint(a3)),
          "r"(__float_as_uint(b0)), "r"(__float_as_uint(b1)));
}
__device__ __forceinline__ int dperm(int l) {   // logical -> stored position
    return (l < 4) ? 2 * l : 2 * l - 7;
}

// ---------------------------------------------------------------------------
// Pre-round x to tf32 and store k-permuted into g_Xr
// ---------------------------------------------------------------------------
__global__ void round_x(const float* __restrict__ x)
{
    int i = (blockIdx.x * 256 + threadIdx.x) * 4;
    float4 v = *(const float4*)(x + i);
    const int l     = i & 7;                 // 0 or 4
    const int base  = i - l;
    const int start = (l < 4) ? 0 : 1;
    g_Xr[base + start + 0] = cvt_tf32(v.x);
    g_Xr[base + start + 2] = cvt_tf32(v.y);
    g_Xr[base + start + 4] = cvt_tf32(v.z);
    g_Xr[base + start + 6] = cvt_tf32(v.w);
}

// ---------------------------------------------------------------------------
// Weight transpose, tf32 pre-round, k-permuted: src[K][N] -> dst[N][Kperm]
// ---------------------------------------------------------------------------
template <int W>
__global__ void transpose_tf32(const float* __restrict__ src, int K, int N)
{
    __shared__ float t[32][33];
    float* dst = (W == 0) ? g_WaT : g_WpT;
    const int x = threadIdx.x, y = threadIdx.y;
    const int n0 = blockIdx.x * 32, k0 = blockIdx.y * 32;
#pragma unroll
    for (int i = 0; i < 4; i++) {
        float v = src[(size_t)(k0 + y + i * 8) * N + n0 + x];
        t[y + i * 8][x] = cvt_tf32(v);
    }
    __syncthreads();
    const int px = (x & ~7) + dperm(x & 7);
#pragma unroll
    for (int i = 0; i < 4; i++)
        dst[(size_t)(n0 + y + i * 8) * K + k0 + px] = t[x][y + i * 8];
}

// ---------------------------------------------------------------------------
// tf32 mma.sync GEMM: D[M,N] = A[M,1024] @ BT[N,1024]^T + bias[N]
// CTA tile 256x128, 8 warps (4x2), warp tile 64x64.
// 4-stage cp.async pipeline, XOR-swizzled pad-free smem, float2 fragment loads.
// MODE 0: A = g_Xr, BT = g_WaT, scatter (tf32-rounded) to g_Q/g_K/g_V
// MODE 1: A = g_CTX, BT = g_WpT, write Cout row-major
// ---------------------------------------------------------------------------
#define CM 256
#define CN 128
#define TK 32
#define SPIPE 4
#define A_BYTES (CM * TK * 4)           // 32768
#define B_BYTES (CN * TK * 4)           // 16384
#define STG_B   (A_BYTES + B_BYTES)     // 49152
#define GSMEM_BYTES (SPIPE * STG_B)     // 196608
#define NSTAGE (EMB / TK)               // 32

template <int MODE>
__global__ void __launch_bounds__(256, 1)
gemm_tc(const float* __restrict__ bias, float* __restrict__ Cout)
{
    extern __shared__ float smf[];
    const uint32_t sb = smem_u32(smf);
    const int tid  = threadIdx.x;
    const int wid  = tid >> 5;
    const int lane = tid & 31;
    const int gid  = lane >> 2;          // 0..7
    const int tig  = lane & 3;           // 0..3
    const int warp_m = (wid >> 1) * 64;  // 4 warp-rows
    const int warp_n = (wid & 1) * 64;   // 2 warp-cols
    const int m0 = blockIdx.y * CM;
    const int n0 = blockIdx.x * CN;

    const float* A  = (MODE == 1) ? g_CTX : g_Xr;
    const float* BT = (MODE == 1) ? g_WpT : g_WaT;

    float acc[4][8][4];
#pragma unroll
    for (int mt = 0; mt < 4; mt++)
#pragma unroll
        for (int nt = 0; nt < 8; nt++)
#pragma unroll
            for (int r = 0; r < 4; r++) acc[mt][nt][r] = 0.0f;

    // loaders: every thread owns A row tid; threads <128 also own B row tid
    const float* gA = A + (size_t)(m0 + tid) * EMB;
    const float* gB = BT + (size_t)(n0 + (tid & 127)) * EMB;
    const uint32_t swz  = (uint32_t)(tid & 3) << 1;      // float4-chunk xor
    const uint32_t aoff = (uint32_t)tid * 128;
    const uint32_t boff = A_BYTES + (uint32_t)(tid & 127) * 128;
    const bool doB = (tid < 128);

#define ISSUE(s_)                                                              \
    {                                                                          \
        uint32_t st = sb + (uint32_t)(((s_) % SPIPE) * STG_B);                 \
        const float* ga = gA + (s_) * TK;                                      \
        _Pragma("unroll")                                                      \
        for (int c = 0; c < 8; c++)                                            \
            cp16(st + aoff + (((uint32_t)c ^ swz) << 4), ga + c * 4);          \
        if (doB) {                                                             \
            const float* gb = gB + (s_) * TK;                                  \
            _Pragma("unroll")                                                  \
            for (int c = 0; c < 8; c++)                                        \
                cp16(st + boff + (((uint32_t)c ^ swz) << 4), gb + c * 4);      \
        }                                                                      \
    }

    ISSUE(0); asm volatile("cp.async.commit_group;" ::: "memory");
    ISSUE(1); asm volatile("cp.async.commit_group;" ::: "memory");
    ISSUE(2); asm volatile("cp.async.commit_group;" ::: "memory");
    asm volatile("cp.async.wait_group 2;" ::: "memory");
    __syncthreads();

    const uint32_t g3 = (uint32_t)(gid & 3) << 2;        // float2 xor

    for (int s = 0; s < NSTAGE; s++) {
        if (s + 3 < NSTAGE) ISSUE(s + 3);
        asm volatile("cp.async.commit_group;" ::: "memory");

        const float2* St2 = (const float2*)((const char*)smf + (s % SPIPE) * STG_B);
        const float2* Bt2 = St2 + (A_BYTES / 8);
#pragma unroll
        for (int kk = 0; kk < 4; kk++) {
            const uint32_t jx = ((uint32_t)(kk * 4 + tig)) ^ g3;
            float2 af[4][2], bf[8];
#pragma unroll
            for (int mt = 0; mt < 4; mt++) {
                const int m = warp_m + mt * 16 + gid;
                af[mt][0] = St2[m * 16 + jx];
                af[mt][1] = St2[(m + 8) * 16 + jx];
            }
#pragma unroll
            for (int nt = 0; nt < 8; nt++) {
                const int n = warp_n + nt * 8 + gid;
                bf[nt] = Bt2[n * 16 + jx];
            }
#pragma unroll
            for (int mt = 0; mt < 4; mt++)
#pragma unroll
                for (int nt = 0; nt < 8; nt++)
                    mma_tf32(acc[mt][nt][0], acc[mt][nt][1],
                             acc[mt][nt][2], acc[mt][nt][3],
                             af[mt][0].x, af[mt][1].x, af[mt][0].y, af[mt][1].y,
                             bf[nt].x, bf[nt].y);
        }
        asm volatile("cp.async.wait_group 2;" ::: "memory");
        __syncthreads();
    }
#undef ISSUE

#pragma unroll
    for (int mt = 0; mt < 4; mt++) {
        const int r0 = m0 + warp_m + mt * 16 + gid;
        const int r1 = r0 + 8;
#pragma unroll
        for (int nt = 0; nt < 8; nt++) {
            const int nb = n0 + warp_n + nt * 8;
            const int c  = nb + tig * 2;
            const float2 bv = *(const float2*)(bias + c);
            float2 o0, o1;
            o0.x = acc[mt][nt][0] + bv.x;
            o0.y = acc[mt][nt][1] + bv.y;
            o1.x = acc[mt][nt][2] + bv.x;
            o1.y = acc[mt][nt][3] + bv.y;
            if (MODE == 1) {
                *(float2*)(Cout + (size_t)r0 * EMB + c) = o0;
                *(float2*)(Cout + (size_t)r1 * EMB + c) = o1;
            } else {
                o0.x = cvt_tf32(o0.x); o0.y = cvt_tf32(o0.y);
                o1.x = cvt_tf32(o1.x); o1.y = cvt_tf32(o1.y);
                const int which = nb >> 10;
                const int e  = nb & 1023;
                const int h  = e >> 6;
                const int dd = (e & 63) + tig * 2;
                float* dst = (which == 0) ? g_Q : (which == 1) ? g_K : g_V;
                const int b0i = r0 >> 11, s0i = r0 & 2047;
                const int b1i = r1 >> 11, s1i = r1 & 2047;
                *(float2*)(dst + (((size_t)(b0i * NHEAD + h)) * S_LEN + s0i) * HDIM + dd) = o0;
                *(float2*)(dst + (((size_t)(b1i * NHEAD + h)) * S_LEN + s1i) * HDIM + dd) = o1;
            }
        }
    }
}

// ---------------------------------------------------------------------------
// Flash attention (causal) with tf32 mma.sync — logic unchanged from R5/R6.
// Only change: epilogue writes g_CTX with k-PERMUTED columns (feeds gemm_tc<1>).
// ---------------------------------------------------------------------------
#define QPAD 68
#define KPAD 68
#define VPAD 72
#define FLASH_SMEM ((128 * QPAD + 64 * KPAD + 64 * VPAD) * 4)   // 70656

__global__ void __launch_bounds__(256)
flash_kernel()
{
    extern __shared__ float sm[];
    float* Qs = sm;                      // [128][68]
    float* Ks = Qs + 128 * QPAD;         // [64][68]
    float* Vs = Ks + 64 * KPAD;          // [64][72]

    const int tid  = threadIdx.x;
    const int wid  = tid >> 5;
    const int lane = tid & 31;
    const int gid  = lane >> 2;
    const int tig  = lane & 3;
    const int qt   = blockIdx.x;
    const int bh   = blockIdx.y;
    const int q0   = qt * 128;

    const float* Qg = g_Q + (size_t)bh * S_LEN * HDIM;
    const float* Kg = g_K + (size_t)bh * S_LEN * HDIM;
    const float* Vg = g_V + (size_t)bh * S_LEN * HDIM;

#pragma unroll
    for (int it = 0; it < 8; it++) {
        int id  = tid + it * 256;
        int row = id >> 4;
        int c4  = id & 15;
        float4 v = *(const float4*)(Qg + (size_t)(q0 + row) * HDIM + c4 * 4);
        *(float4*)(&Qs[row * QPAD + c4 * 4]) = v;
    }
    __syncthreads();

    const int qrow = wid * 16 + gid;
    float qa[8][4];
#pragma unroll
    for (int kk = 0; kk < 8; kk++) {
        qa[kk][0] = Qs[qrow * QPAD + kk * 8 + tig];
        qa[kk][1] = Qs[(qrow + 8) * QPAD + kk * 8 + tig];
        qa[kk][2] = Qs[qrow * QPAD + kk * 8 + tig + 4];
        qa[kk][3] = Qs[(qrow + 8) * QPAD + kk * 8 + tig + 4];
    }

    float m0v = -1e30f, m1v = -1e30f, l0 = 0.0f, l1 = 0.0f;
    float o[8][4];
#pragma unroll
    for (int nt = 0; nt < 8; nt++)
#pragma unroll
        for (int r = 0; r < 4; r++) o[nt][r] = 0.0f;

    const int r0g = q0 + wid * 16 + gid;
    const int nkt = 2 * (qt + 1);

    for (int kt = 0; kt < nkt; kt++) {
        const int k0 = kt * 64;
        __syncthreads();
#pragma unroll
        for (int it = 0; it < 4; it++) {
            int id  = tid + it * 256;
            int row = id >> 4;
            int c4  = id & 15;
            *(float4*)(&Ks[row * KPAD + c4 * 4]) =
                *(const float4*)(Kg + (size_t)(k0 + row) * HDIM + c4 * 4);
            *(float4*)(&Vs[row * VPAD + c4 * 4]) =
                *(const float4*)(Vg + (size_t)(k0 + row) * HDIM + c4 * 4);
        }
        __syncthreads();

        float s[8][4];
#pragma unroll
        for (int nt = 0; nt < 8; nt++)
#pragma unroll
            for (int r = 0; r < 4; r++) s[nt][r] = 0.0f;

#pragma unroll
        for (int kk = 0; kk < 8; kk++) {
            const int kb = kk * 8 + tig;
#pragma unroll
            for (int nt = 0; nt < 8; nt++) {
                const int key = nt * 8 + gid;
                float b0 = Ks[key * KPAD + kb];
                float b1 = Ks[key * KPAD + kb + 4];
                mma_tf32(s[nt][0], s[nt][1], s[nt][2], s[nt][3],
                         qa[kk][0], qa[kk][1], qa[kk][2], qa[kk][3], b0, b1);
            }
        }

        const bool domask = (k0 + 63) > r0g;
#pragma unroll
        for (int nt = 0; nt < 8; nt++) {
            const int c0 = k0 + nt * 8 + tig * 2;
            s[nt][0] *= 0.125f; s[nt][1] *= 0.125f;
            s[nt][2] *= 0.125f; s[nt][3] *= 0.125f;
            if (domask) {
                if (c0 > r0g)         s[nt][0] = -1e30f;
                if (c0 + 1 > r0g)     s[nt][1] = -1e30f;
                if (c0 > r0g + 8)     s[nt][2] = -1e30f;
                if (c0 + 1 > r0g + 8) s[nt][3] = -1e30f;
            }
        }

        float mx0 = -1e30f, mx1 = -1e30f;
#pragma unroll
        for (int nt = 0; nt < 8; nt++) {
            mx0 = fmaxf(mx0, fmaxf(s[nt][0], s[nt][1]));
            mx1 = fmaxf(mx1, fmaxf(s[nt][2], s[nt][3]));
        }
        mx0 = fmaxf(mx0, __shfl_xor_sync(0xffffffffu, mx0, 1));
        mx0 = fmaxf(mx0, __shfl_xor_sync(0xffffffffu, mx0, 2));
        mx1 = fmaxf(mx1, __shfl_xor_sync(0xffffffffu, mx1, 1));
        mx1 = fmaxf(mx1, __shfl_xor_sync(0xffffffffu, mx1, 2));

        const float mn0 = fmaxf(m0v, mx0);
        const float mn1 = fmaxf(m1v, mx1);
        const float al0 = __expf(m0v - mn0);
        const float al1 = __expf(m1v - mn1);
        m0v = mn0; m1v = mn1;

        float sum0 = 0.0f, sum1 = 0.0f;
#pragma unroll
        for (int nt = 0; nt < 8; nt++) {
            s[nt][0] = cvt_tf32(__expf(s[nt][0] - mn0));
            s[nt][1] = cvt_tf32(__expf(s[nt][1] - mn0));
            s[nt][2] = cvt_tf32(__expf(s[nt][2] - mn1));
            s[nt][3] = cvt_tf32(__expf(s[nt][3] - mn1));
            sum0 += s[nt][0] + s[nt][1];
            sum1 += s[nt][2] + s[nt][3];
        }
        sum0 += __shfl_xor_sync(0xffffffffu, sum0, 1);
        sum0 += __shfl_xor_sync(0xffffffffu, sum0, 2);
        sum1 += __shfl_xor_sync(0xffffffffu, sum1, 1);
        sum1 += __shfl_xor_sync(0xffffffffu, sum1, 2);
        l0 = l0 * al0 + sum0;
        l1 = l1 * al1 + sum1;

#pragma unroll
        for (int nt = 0; nt < 8; nt++) {
            o[nt][0] *= al0; o[nt][1] *= al0;
            o[nt][2] *= al1; o[nt][3] *= al1;
        }

        const int base = lane & ~3;
        const int srcA = base + (tig >> 1);
        const int srcB = srcA + 2;
        const bool odd = (tig & 1);
#pragma unroll
        for (int kc = 0; kc < 8; kc++) {
            float u0 = __shfl_sync(0xffffffffu, s[kc][0], srcA);
            float u1 = __shfl_sync(0xffffffffu, s[kc][1], srcA);
            float a0 = odd ? u1 : u0;
            float v0 = __shfl_sync(0xffffffffu, s[kc][0], srcB);
            float v1 = __shfl_sync(0xffffffffu, s[kc][1], srcB);
            float a2 = odd ? v1 : v0;
            float w0 = __shfl_sync(0xffffffffu, s[kc][2], srcA);
            float w1 = __shfl_sync(0xffffffffu, s[kc][3], srcA);
            float a1 = odd ? w1 : w0;
            float x0 = __shfl_sync(0xffffffffu, s[kc][2], srcB);
            float x1 = __shfl_sync(0xffffffffu, s[kc][3], srcB);
            float a3 = odd ? x1 : x0;
#pragma unroll
            for (int nt = 0; nt < 8; nt++) {
                float b0 = Vs[(kc * 8 + tig) * VPAD + nt * 8 + gid];
                float b1 = Vs[(kc * 8 + tig + 4) * VPAD + nt * 8 + gid];
                mma_tf32(o[nt][0], o[nt][1], o[nt][2], o[nt][3],
                         a0, a1, a2, a3, b0, b1);
            }
        }
    }

    // write ctx k-PERMUTED (tf32-rounded; feeds permuted-layout gemm_tc<1>)
    const int b = bh >> 4, h = bh & 15;
    const float inv0 = 1.0f / l0;
    const float inv1 = 1.0f / l1;
    const int r1g = r0g + 8;
    const int p0 = dperm(2 * tig);
    const int p1 = dperm(2 * tig + 1);
#pragma unroll
    for (int nt = 0; nt < 8; nt++) {
        const int cb = h * HDIM + nt * 8;
        float* row0 = g_CTX + ((size_t)(b * S_LEN + r0g)) * EMB + cb;
        float* row1 = g_CTX + ((size_t)(b * S_LEN + r1g)) * EMB + cb;
        row0[p0] = cvt_tf32(o[nt][0] * inv0);
        row0[p1] = cvt_tf32(o[nt][1] * inv0);
        row1[p0] = cvt_tf32(o[nt][2] * inv1);
        row1[p1] = cvt_tf32(o[nt][3] * inv1);
    }
}

// ---------------------------------------------------------------------------
extern "C" void kernel_launch(void* const* d_in, const int* in_sizes, int n_in,
                              void* d_out, int out_size)
{
    const float* x      = (const float*)d_in[0];
    const float* w_attn = (const float*)d_in[1];
    const float* b_attn = (const float*)d_in[2];
    const float* w_proj = (const float*)d_in[3];
    const float* b_proj = (const float*)d_in[4];
    float* out = (float*)d_out;

    cudaFuncSetAttribute(gemm_tc<0>, cudaFuncAttributeMaxDynamicSharedMemorySize, GSMEM_BYTES);
    cudaFuncSetAttribute(gemm_tc<1>, cudaFuncAttributeMaxDynamicSharedMemorySize, GSMEM_BYTES);
    cudaFuncSetAttribute(flash_kernel, cudaFuncAttributeMaxDynamicSharedMemorySize, FLASH_SMEM);

    // 0) pre-round x (permuted), transpose+round weights (permuted)
    round_x<<<ROWS * EMB / 4 / 256, 256>>>(x);
    transpose_tf32<0><<<dim3(3 * EMB / 32, EMB / 32), dim3(32, 8)>>>(w_attn, EMB, 3 * EMB);
    transpose_tf32<1><<<dim3(EMB / 32, EMB / 32),     dim3(32, 8)>>>(w_proj, EMB, EMB);

    // 1) QKV GEMM -> g_Q/g_K/g_V (normal layout, tf32-rounded)
    gemm_tc<0><<<dim3(3 * EMB / CN, ROWS / CM), 256, GSMEM_BYTES>>>(b_attn, nullptr);

    // 2) causal flash attention -> g_CTX (permuted)
    flash_kernel<<<dim3(S_LEN / 128, B_SZ * NHEAD), 256, FLASH_SMEM>>>();

    // 3) projection GEMM -> out
    gemm_tc<1><<<dim3(EMB / CN, ROWS / CM), 256, GSMEM_BYTES>>>(b_proj, out);
}

// round 8
// speedup vs baseline: 5.1521x; 2.0070x over previous
#include <cuda_runtime.h>
#include <cuda_fp16.h>
#include <cstdint>
#include <math.h>

// Problem constants
#define B_SZ   2
#define S_LEN  2048
#define EMB    1024
#define NHEAD  16
#define HDIM   64
#define ROWS   (B_SZ * S_LEN)          // 4096

// Scratch (device globals -> no allocation). All fp16 operand tensors.
__device__ __half g_Qh [B_SZ * NHEAD * S_LEN * HDIM];   // [b,h,s,d]
__device__ __half g_Kh [B_SZ * NHEAD * S_LEN * HDIM];   // [b,h,s,d]
__device__ __half g_Vth[B_SZ * NHEAD * HDIM * S_LEN];   // [b,h,d,s]  (transposed!)
__device__ __half g_CTXh[ROWS * EMB];
__device__ __half g_Xh  [ROWS * EMB];
__device__ __half g_WaTh[3 * EMB * EMB];                // w_attn^T [3072][1024]
__device__ __half g_WpTh[EMB * EMB];                    // w_proj^T [1024][1024]

// ---------------------------------------------------------------------------
// Helpers
// ---------------------------------------------------------------------------
__device__ __forceinline__ uint32_t smem_u32(const void* p) {
    uint32_t a;
    asm("{ .reg .u64 t; cvta.to.shared.u64 t, %1; cvt.u32.u64 %0, t; }"
        : "=r"(a) : "l"(p));
    return a;
}
__device__ __forceinline__ void cp16(uint32_t smaddr, const void* gaddr) {
    asm volatile("cp.async.cg.shared.global [%0], [%1], 16;"
                 :: "r"(smaddr), "l"(gaddr) : "memory");
}
__device__ __forceinline__ uint32_t h2u(__half2 h) {
    return *reinterpret_cast<uint32_t*>(&h);
}
// m16n8k16 fp16->fp32: a0=(gid,2t..+1) a1=(gid+8,..) a2=(gid,2t+8..) a3=(gid+8,..)
//                      b0=(k 2t..+1,col gid) b1=(k 2t+8..+9,col gid)
__device__ __forceinline__ void mma_f16(float& d0, float& d1, float& d2, float& d3,
                                        uint32_t a0, uint32_t a1, uint32_t a2, uint32_t a3,
                                        uint32_t b0, uint32_t b1) {
    asm volatile(
        "mma.sync.aligned.m16n8k16.row.col.f32.f16.f16.f32 "
        "{%0,%1,%2,%3},{%4,%5,%6,%7},{%8,%9},{%0,%1,%2,%3};"
        : "+f"(d0), "+f"(d1), "+f"(d2), "+f"(d3)
        : "r"(a0), "r"(a1), "r"(a2), "r"(a3), "r"(b0), "r"(b1));
}
// XOR swizzle within a 128B row: 16B chunk index ^ (row & 7)
__device__ __forceinline__ uint32_t swz(int row, int bc) {
    return (uint32_t)(row * 128 + (((bc >> 4) ^ (row & 7)) << 4) + (bc & 15));
}

// ---------------------------------------------------------------------------
// Prep: x -> fp16
// ---------------------------------------------------------------------------
__global__ void cvt_x(const float* __restrict__ x)
{
    int i = (blockIdx.x * 256 + threadIdx.x) * 4;
    float4 v = *(const float4*)(x + i);
    __half2* o = (__half2*)(g_Xh + i);
    o[0] = __floats2half2_rn(v.x, v.y);
    o[1] = __floats2half2_rn(v.z, v.w);
}

// Weight transpose -> fp16: src[K][N] -> dst[N][K]
template <int W>
__global__ void transpose_h(const float* __restrict__ src, int K, int N)
{
    __shared__ float t[32][33];
    __half* dst = (W == 0) ? g_WaTh : g_WpTh;
    const int x = threadIdx.x, y = threadIdx.y;
    const int n0 = blockIdx.x * 32, k0 = blockIdx.y * 32;
#pragma unroll
    for (int i = 0; i < 4; i++)
        t[y + i * 8][x] = src[(size_t)(k0 + y + i * 8) * N + n0 + x];
    __syncthreads();
#pragma unroll
    for (int i = 0; i < 4; i++)
        dst[(size_t)(n0 + y + i * 8) * K + k0 + x] = __float2half_rn(t[x][y + i * 8]);
}

// ---------------------------------------------------------------------------
// fp16 mma.sync GEMM: D[M,N] = A[M,1024] @ BT[N,1024]^T + bias[N]
// CTA 128x128, 8 warps (2x4, warp 64x32), TK=64, 3-stage cp.async.
// MODE 0: A=g_Xh, BT=g_WaTh -> Q/K fp16 [s][d]; V fp16 transposed [d][s]
// MODE 1: A=g_CTXh, BT=g_WpTh -> Cout fp32 row-major
// ---------------------------------------------------------------------------
#define CMM 128
#define CNN 128
#define TKK 64
#define A_BY (CMM * TKK * 2)            // 16384
#define STG_B (2 * A_BY)                // 32768
#define SPIPE 3
#define GSMEM_BYTES (SPIPE * STG_B)     // 98304
#define NSTAGE (EMB / TKK)              // 16

template <int MODE>
__global__ void __launch_bounds__(256, 2)
gemm_h(const float* __restrict__ bias, float* __restrict__ Cout)
{
    extern __shared__ char smc[];
    const uint32_t sb = smem_u32(smc);
    const int tid  = threadIdx.x;
    const int wid  = tid >> 5;
    const int lane = tid & 31;
    const int gid  = lane >> 2;
    const int tig  = lane & 3;
    const int warp_m = (wid >> 2) * 64;
    const int warp_n = (wid & 3) * 32;
    const int m0 = blockIdx.y * CMM;
    const int n0 = blockIdx.x * CNN;

    const __half* A  = (MODE == 1) ? g_CTXh : g_Xh;
    const __half* BT = (MODE == 1) ? g_WpTh : g_WaTh;

    float acc[4][4][4];
#pragma unroll
    for (int mt = 0; mt < 4; mt++)
#pragma unroll
        for (int nt = 0; nt < 4; nt++)
#pragma unroll
            for (int r = 0; r < 4; r++) acc[mt][nt][r] = 0.0f;

    // loaders: row = tid>>1 (128 rows), 4 chunks of 16B each for A and B
    const int lrow = tid >> 1;
    const int cb   = (tid & 1) * 4;
    const __half* gA = A  + (size_t)(m0 + lrow) * EMB;
    const __half* gB = BT + (size_t)(n0 + lrow) * EMB;

#define ISSUE(s_)                                                              \
    {                                                                          \
        uint32_t st = sb + (uint32_t)(((s_) % SPIPE) * STG_B);                 \
        const __half* ga = gA + (s_) * TKK;                                    \
        const __half* gb = gB + (s_) * TKK;                                    \
        _Pragma("unroll")                                                      \
        for (int c = 0; c < 4; c++) {                                          \
            cp16(st + swz(lrow, (cb + c) * 16), ga + (cb + c) * 8);            \
            cp16(st + A_BY + swz(lrow, (cb + c) * 16), gb + (cb + c) * 8);     \
        }                                                                      \
    }

    ISSUE(0); asm volatile("cp.async.commit_group;" ::: "memory");
    ISSUE(1); asm volatile("cp.async.commit_group;" ::: "memory");
    asm volatile("cp.async.wait_group 1;" ::: "memory");
    __syncthreads();

    for (int s = 0; s < NSTAGE; s++) {
        if (s + 2 < NSTAGE) ISSUE(s + 2);
        asm volatile("cp.async.commit_group;" ::: "memory");

        const char* stA = smc + (s % SPIPE) * STG_B;
        const char* stB = stA + A_BY;
#pragma unroll
        for (int g = 0; g < 4; g++) {
            const int bc = 4 * tig + 32 * g;
            uint32_t af[4][4], bf[4][2];
#pragma unroll
            for (int mt = 0; mt < 4; mt++) {
                const int m = warp_m + mt * 16 + gid;
                af[mt][0] = *(const uint32_t*)(stA + swz(m,     bc));
                af[mt][1] = *(const uint32_t*)(stA + swz(m + 8, bc));
                af[mt][2] = *(const uint32_t*)(stA + swz(m,     bc + 16));
                af[mt][3] = *(const uint32_t*)(stA + swz(m + 8, bc + 16));
            }
#pragma unroll
            for (int nt = 0; nt < 4; nt++) {
                const int n = warp_n + nt * 8 + gid;
                bf[nt][0] = *(const uint32_t*)(stB + swz(n, bc));
                bf[nt][1] = *(const uint32_t*)(stB + swz(n, bc + 16));
            }
#pragma unroll
            for (int mt = 0; mt < 4; mt++)
#pragma unroll
                for (int nt = 0; nt < 4; nt++)
                    mma_f16(acc[mt][nt][0], acc[mt][nt][1],
                            acc[mt][nt][2], acc[mt][nt][3],
                            af[mt][0], af[mt][1], af[mt][2], af[mt][3],
                            bf[nt][0], bf[nt][1]);
        }
        asm volatile("cp.async.wait_group 1;" ::: "memory");
        __syncthreads();
    }
#undef ISSUE

#pragma unroll
    for (int mt = 0; mt < 4; mt++) {
        const int r0 = m0 + warp_m + mt * 16 + gid;
        const int r1 = r0 + 8;
#pragma unroll
        for (int nt = 0; nt < 4; nt++) {
            const int nb = n0 + warp_n + nt * 8;
            const int c  = nb + tig * 2;
            const float2 bv = *(const float2*)(bias + c);
            float2 o0, o1;
            o0.x = acc[mt][nt][0] + bv.x;
            o0.y = acc[mt][nt][1] + bv.y;
            o1.x = acc[mt][nt][2] + bv.x;
            o1.y = acc[mt][nt][3] + bv.y;
            if (MODE == 1) {
                *(float2*)(Cout + (size_t)r0 * EMB + c) = o0;
                *(float2*)(Cout + (size_t)r1 * EMB + c) = o1;
            } else {
                const int which = nb >> 10;
                const int e  = nb & 1023;
                const int h  = e >> 6;
                const int dd = (e & 63) + tig * 2;
                const int b0i = r0 >> 11, s0i = r0 & 2047;
                const int b1i = r1 >> 11, s1i = r1 & 2047;
                if (which == 2) {
                    // V transposed: [b,h,d,s]
                    __half* vb0 = g_Vth + ((size_t)(b0i * NHEAD + h) * HDIM + dd) * S_LEN;
                    __half* vb1 = g_Vth + ((size_t)(b1i * NHEAD + h) * HDIM + dd) * S_LEN;
                    vb0[s0i]          = __float2half_rn(o0.x);
                    vb0[S_LEN + s0i]  = __float2half_rn(o0.y);
                    vb1[s1i]          = __float2half_rn(o1.x);
                    vb1[S_LEN + s1i]  = __float2half_rn(o1.y);
                } else {
                    __half* dst = (which == 0) ? g_Qh : g_Kh;
                    *(__half2*)(dst + ((size_t)(b0i * NHEAD + h) * S_LEN + s0i) * HDIM + dd)
                        = __floats2half2_rn(o0.x, o0.y);
                    *(__half2*)(dst + ((size_t)(b1i * NHEAD + h) * S_LEN + s1i) * HDIM + dd)
                        = __floats2half2_rn(o1.x, o1.y);
                }
            }
        }
    }
}

// ---------------------------------------------------------------------------
// Flash attention (causal), fp16 mma.sync m16n8k16.
// CTA 256 thr / 8 warps, q-tile 128 (16 q-rows per warp), k-tile 64, D=64.
// Q frags in regs; K [key][d] and Vt [d][key] double-buffered via cp.async.
// P acc-layout == fp16 A-frag layout => NO shuffles for P.
// ---------------------------------------------------------------------------
#define FQ_BY (128 * 128)               // Q tile 16KB
#define FK_BY (64 * 128)                // 8KB per K buffer
#define KOFF  FQ_BY
#define VOFF  (FQ_BY + 2 * FK_BY)
#define FLASH_SMEM (FQ_BY + 4 * FK_BY)  // 49152

__global__ void __launch_bounds__(256)
flash_h()
{
    extern __shared__ char smc[];
    const uint32_t sb = smem_u32(smc);
    const int tid  = threadIdx.x;
    const int wid  = tid >> 5;
    const int lane = tid & 31;
    const int gid  = lane >> 2;
    const int tig  = lane & 3;
    const int qt   = blockIdx.x;
    const int bh   = blockIdx.y;
    const int q0   = qt * 128;

    const __half* Qg = g_Qh  + (size_t)bh * S_LEN * HDIM;
    const __half* Kg = g_Kh  + (size_t)bh * S_LEN * HDIM;
    const __half* Vg = g_Vth + (size_t)bh * HDIM * S_LEN;

    // Q load: row = tid>>1, 4 chunks
    {
        const int r = tid >> 1, c0 = (tid & 1) * 4;
        const __half* gq = Qg + (size_t)(q0 + r) * HDIM;
#pragma unroll
        for (int c = 0; c < 4; c++)
            cp16(sb + swz(r, (c0 + c) * 16), gq + (c0 + c) * 8);
    }

#define ISSUE_KV(kt_, buf_)                                                    \
    {                                                                          \
        const int r = tid >> 2, c0 = (tid & 3) * 2;                            \
        const __half* gk = Kg + (size_t)((kt_) * 64 + r) * HDIM;               \
        const __half* gv = Vg + (size_t)r * S_LEN + (kt_) * 64;                \
        _Pragma("unroll")                                                      \
        for (int c = 0; c < 2; c++) {                                          \
            cp16(sb + KOFF + (buf_) * FK_BY + swz(r, (c0 + c) * 16),           \
                 gk + (c0 + c) * 8);                                           \
            cp16(sb + VOFF + (buf_) * FK_BY + swz(r, (c0 + c) * 16),           \
                 gv + (c0 + c) * 8);                                           \
        }                                                                      \
    }

    ISSUE_KV(0, 0);
    asm volatile("cp.async.commit_group;" ::: "memory");
    asm volatile("cp.async.wait_group 0;" ::: "memory");
    __syncthreads();

    // Q A-fragments: 4 k-groups x 4 u32
    const int qrow = wid * 16 + gid;
    uint32_t qa[4][4];
#pragma unroll
    for (int g = 0; g < 4; g++) {
        const int bc = 4 * tig + 32 * g;
        qa[g][0] = *(const uint32_t*)(smc + swz(qrow,     bc));
        qa[g][1] = *(const uint32_t*)(smc + swz(qrow + 8, bc));
        qa[g][2] = *(const uint32_t*)(smc + swz(qrow,     bc + 16));
        qa[g][3] = *(const uint32_t*)(smc + swz(qrow + 8, bc + 16));
    }

    float m0v = -1e30f, m1v = -1e30f, l0 = 0.0f, l1 = 0.0f;
    float o[8][4];
#pragma unroll
    for (int nt = 0; nt < 8; nt++)
#pragma unroll
        for (int r = 0; r < 4; r++) o[nt][r] = 0.0f;

    const int r0g = q0 + wid * 16 + gid;
    const int nkt = 2 * (qt + 1);

    for (int kt = 0; kt < nkt; kt++) {
        asm volatile("cp.async.wait_group 0;" ::: "memory");
        __syncthreads();                       // tile kt ready; all done with kt-1
        if (kt + 1 < nkt) ISSUE_KV(kt + 1, (kt + 1) & 1);
        asm volatile("cp.async.commit_group;" ::: "memory");

        const char* Ks = smc + KOFF + (kt & 1) * FK_BY;
        const char* Vs = smc + VOFF + (kt & 1) * FK_BY;
        const int k0 = kt * 64;

        // S = Q K^T : 8 key-tiles of 8
        float s[8][4];
#pragma unroll
        for (int nt = 0; nt < 8; nt++)
#pragma unroll
            for (int r = 0; r < 4; r++) s[nt][r] = 0.0f;

#pragma unroll
        for (int g = 0; g < 4; g++) {
            const int bc = 4 * tig + 32 * g;
#pragma unroll
            for (int nt = 0; nt < 8; nt++) {
                const int key = nt * 8 + gid;
                uint32_t b0 = *(const uint32_t*)(Ks + swz(key, bc));
                uint32_t b1 = *(const uint32_t*)(Ks + swz(key, bc + 16));
                mma_f16(s[nt][0], s[nt][1], s[nt][2], s[nt][3],
                        qa[g][0], qa[g][1], qa[g][2], qa[g][3], b0, b1);
            }
        }

        // scale + causal mask
        const bool domask = (k0 + 63) > r0g;
#pragma unroll
        for (int nt = 0; nt < 8; nt++) {
            const int c0 = k0 + nt * 8 + tig * 2;
            s[nt][0] *= 0.125f; s[nt][1] *= 0.125f;
            s[nt][2] *= 0.125f; s[nt][3] *= 0.125f;
            if (domask) {
                if (c0 > r0g)         s[nt][0] = -1e30f;
                if (c0 + 1 > r0g)     s[nt][1] = -1e30f;
                if (c0 > r0g + 8)     s[nt][2] = -1e30f;
                if (c0 + 1 > r0g + 8) s[nt][3] = -1e30f;
            }
        }

        // online softmax (rows gid / gid+8)
        float mx0 = -1e30f, mx1 = -1e30f;
#pragma unroll
        for (int nt = 0; nt < 8; nt++) {
            mx0 = fmaxf(mx0, fmaxf(s[nt][0], s[nt][1]));
            mx1 = fmaxf(mx1, fmaxf(s[nt][2], s[nt][3]));
        }
        mx0 = fmaxf(mx0, __shfl_xor_sync(0xffffffffu, mx0, 1));
        mx0 = fmaxf(mx0, __shfl_xor_sync(0xffffffffu, mx0, 2));
        mx1 = fmaxf(mx1, __shfl_xor_sync(0xffffffffu, mx1, 1));
        mx1 = fmaxf(mx1, __shfl_xor_sync(0xffffffffu, mx1, 2));

        const float mn0 = fmaxf(m0v, mx0);
        const float mn1 = fmaxf(m1v, mx1);
        const float al0 = __expf(m0v - mn0);
        const float al1 = __expf(m1v - mn1);
        m0v = mn0; m1v = mn1;

        // P = exp(S - m), as fp16 pairs (acc layout == A-frag layout)
        uint32_t ph[8][2];
        float sum0 = 0.0f, sum1 = 0.0f;
#pragma unroll
        for (int nt = 0; nt < 8; nt++) {
            __half2 h01 = __floats2half2_rn(__expf(s[nt][0] - mn0),
                                            __expf(s[nt][1] - mn0));
            __half2 h23 = __floats2half2_rn(__expf(s[nt][2] - mn1),
                                            __expf(s[nt][3] - mn1));
            ph[nt][0] = h2u(h01);
            ph[nt][1] = h2u(h23);
            float2 f01 = __half22float2(h01);
            float2 f23 = __half22float2(h23);
            sum0 += f01.x + f01.y;
            sum1 += f23.x + f23.y;
        }
        sum0 += __shfl_xor_sync(0xffffffffu, sum0, 1);
        sum0 += __shfl_xor_sync(0xffffffffu, sum0, 2);
        sum1 += __shfl_xor_sync(0xffffffffu, sum1, 1);
        sum1 += __shfl_xor_sync(0xffffffffu, sum1, 2);
        l0 = l0 * al0 + sum0;
        l1 = l1 * al1 + sum1;

#pragma unroll
        for (int nt = 0; nt < 8; nt++) {
            o[nt][0] *= al0; o[nt][1] *= al0;
            o[nt][2] *= al1; o[nt][3] *= al1;
        }

        // O += P V : key-groups g of 16, A = {ph[2g], ph[2g+1]}, B from Vt[d][key]
#pragma unroll
        for (int g = 0; g < 4; g++) {
            const int bc = 4 * tig + 32 * g;
#pragma unroll
            for (int nt = 0; nt < 8; nt++) {
                const int d = nt * 8 + gid;
                uint32_t b0 = *(const uint32_t*)(Vs + swz(d, bc));
                uint32_t b1 = *(const uint32_t*)(Vs + swz(d, bc + 16));
                mma_f16(o[nt][0], o[nt][1], o[nt][2], o[nt][3],
                        ph[2 * g][0], ph[2 * g][1],
                        ph[2 * g + 1][0], ph[2 * g + 1][1], b0, b1);
            }
        }
    }
#undef ISSUE_KV

    // write ctx fp16
    const int b = bh >> 4, h = bh & 15;
    const float inv0 = 1.0f / l0;
    const float inv1 = 1.0f / l1;
    const int r1g = r0g + 8;
#pragma unroll
    for (int nt = 0; nt < 8; nt++) {
        const int col = h * HDIM + nt * 8 + tig * 2;
        *(__half2*)(g_CTXh + ((size_t)(b * S_LEN + r0g)) * EMB + col)
            = __floats2half2_rn(o[nt][0] * inv0, o[nt][1] * inv0);
        *(__half2*)(g_CTXh + ((size_t)(b * S_LEN + r1g)) * EMB + col)
            = __floats2half2_rn(o[nt][2] * inv1, o[nt][3] * inv1);
    }
}

// ---------------------------------------------------------------------------
extern "C" void kernel_launch(void* const* d_in, const int* in_sizes, int n_in,
                              void* d_out, int out_size)
{
    const float* x      = (const float*)d_in[0];
    const float* w_attn = (const float*)d_in[1];
    const float* b_attn = (const float*)d_in[2];
    const float* w_proj = (const float*)d_in[3];
    const float* b_proj = (const float*)d_in[4];
    float* out = (float*)d_out;

    cudaFuncSetAttribute(gemm_h<0>, cudaFuncAttributeMaxDynamicSharedMemorySize, GSMEM_BYTES);
    cudaFuncSetAttribute(gemm_h<1>, cudaFuncAttributeMaxDynamicSharedMemorySize, GSMEM_BYTES);
    cudaFuncSetAttribute(flash_h,   cudaFuncAttributeMaxDynamicSharedMemorySize, FLASH_SMEM);

    // 0) prep: x and transposed weights to fp16
    cvt_x<<<ROWS * EMB / 4 / 256, 256>>>(x);
    transpose_h<0><<<dim3(3 * EMB / 32, EMB / 32), dim3(32, 8)>>>(w_attn, EMB, 3 * EMB);
    transpose_h<1><<<dim3(EMB / 32, EMB / 32),     dim3(32, 8)>>>(w_proj, EMB, EMB);

    // 1) QKV GEMM -> Q,K fp16 [s][d]; V fp16 [d][s]
    gemm_h<0><<<dim3(3 * EMB / CNN, ROWS / CMM), 256, GSMEM_BYTES>>>(b_attn, nullptr);

    // 2) causal flash attention (fp16 mma) -> g_CTXh
    flash_h<<<dim3(S_LEN / 128, B_SZ * NHEAD), 256, FLASH_SMEM>>>();

    // 3) projection GEMM -> out (fp32)
    gemm_h<1><<<dim3(EMB / CNN, ROWS / CMM), 256, GSMEM_BYTES>>>(b_proj, out);
}

// round 9
// speedup vs baseline: 6.0517x; 1.1746x over previous
#include <cuda_runtime.h>
#include <cuda_fp16.h>
#include <cstdint>
#include <math.h>

// Problem constants
#define B_SZ   2
#define S_LEN  2048
#define EMB    1024
#define NHEAD  16
#define HDIM   64
#define ROWS   (B_SZ * S_LEN)          // 4096

// Scratch (device globals -> no allocation). All fp16 operand tensors.
__device__ __half g_Qh [B_SZ * NHEAD * S_LEN * HDIM];   // [b,h,s,d]
__device__ __half g_Kh [B_SZ * NHEAD * S_LEN * HDIM];   // [b,h,s,d]
__device__ __half g_Vth[B_SZ * NHEAD * HDIM * S_LEN];   // [b,h,d,s]  (transposed!)
__device__ __half g_CTXh[ROWS * EMB];
__device__ __half g_Xh  [ROWS * EMB];
__device__ __half g_WaTh[3 * EMB * EMB];                // w_attn^T [3072][1024]
__device__ __half g_WpTh[EMB * EMB];                    // w_proj^T [1024][1024]

// ---------------------------------------------------------------------------
// Helpers
// ---------------------------------------------------------------------------
__device__ __forceinline__ uint32_t smem_u32(const void* p) {
    uint32_t a;
    asm("{ .reg .u64 t; cvta.to.shared.u64 t, %1; cvt.u32.u64 %0, t; }"
        : "=r"(a) : "l"(p));
    return a;
}
__device__ __forceinline__ void cp16(uint32_t smaddr, const void* gaddr) {
    asm volatile("cp.async.cg.shared.global [%0], [%1], 16;"
                 :: "r"(smaddr), "l"(gaddr) : "memory");
}
__device__ __forceinline__ uint32_t h2u(__half2 h) {
    return *reinterpret_cast<uint32_t*>(&h);
}
__device__ __forceinline__ void mma_f16(float& d0, float& d1, float& d2, float& d3,
                                        uint32_t a0, uint32_t a1, uint32_t a2, uint32_t a3,
                                        uint32_t b0, uint32_t b1) {
    asm volatile(
        "mma.sync.aligned.m16n8k16.row.col.f32.f16.f16.f32 "
        "{%0,%1,%2,%3},{%4,%5,%6,%7},{%8,%9},{%0,%1,%2,%3};"
        : "+f"(d0), "+f"(d1), "+f"(d2), "+f"(d3)
        : "r"(a0), "r"(a1), "r"(a2), "r"(a3), "r"(b0), "r"(b1));
}
#define LDSM_X4(r0, r1, r2, r3, addr)                                          \
    asm volatile("ldmatrix.sync.aligned.m8n8.x4.shared.b16 {%0,%1,%2,%3}, [%4];" \
                 : "=r"(r0), "=r"(r1), "=r"(r2), "=r"(r3) : "r"(addr))

// XOR swizzle within a 128B row: 16B chunk index ^ (row & 7)
__device__ __forceinline__ uint32_t swz(int row, int bc) {
    return (uint32_t)(row * 128 + (((bc >> 4) ^ (row & 7)) << 4) + (bc & 15));
}

// ---------------------------------------------------------------------------
// Prep: x -> fp16
// ---------------------------------------------------------------------------
__global__ void cvt_x(const float* __restrict__ x)
{
    int i = (blockIdx.x * 256 + threadIdx.x) * 4;
    float4 v = *(const float4*)(x + i);
    __half2* o = (__half2*)(g_Xh + i);
    o[0] = __floats2half2_rn(v.x, v.y);
    o[1] = __floats2half2_rn(v.z, v.w);
}

// Weight transpose -> fp16: src[K][N] -> dst[N][K]
template <int W>
__global__ void transpose_h(const float* __restrict__ src, int K, int N)
{
    __shared__ float t[32][33];
    __half* dst = (W == 0) ? g_WaTh : g_WpTh;
    const int x = threadIdx.x, y = threadIdx.y;
    const int n0 = blockIdx.x * 32, k0 = blockIdx.y * 32;
#pragma unroll
    for (int i = 0; i < 4; i++)
        t[y + i * 8][x] = src[(size_t)(k0 + y + i * 8) * N + n0 + x];
    __syncthreads();
#pragma unroll
    for (int i = 0; i < 4; i++)
        dst[(size_t)(n0 + y + i * 8) * K + k0 + x] = __float2half_rn(t[x][y + i * 8]);
}

// ---------------------------------------------------------------------------
// fp16 mma.sync GEMM with ldmatrix fragment loads.
// CTA 128x128, 8 warps (2x4, warp 64x32), TK=64, 3-stage cp.async.
// ---------------------------------------------------------------------------
#define CMM 128
#define CNN 128
#define TKK 64
#define A_BY (CMM * TKK * 2)            // 16384
#define STG_B (2 * A_BY)                // 32768
#define SPIPE 3
#define GSMEM_BYTES (SPIPE * STG_B)     // 98304
#define NSTAGE (EMB / TKK)              // 16

template <int MODE>
__global__ void __launch_bounds__(256, 2)
gemm_h(const float* __restrict__ bias, float* __restrict__ Cout)
{
    extern __shared__ char smc[];
    const uint32_t sb = smem_u32(smc);
    const int tid  = threadIdx.x;
    const int wid  = tid >> 5;
    const int lane = tid & 31;
    const int gid  = lane >> 2;
    const int tig  = lane & 3;
    const int warp_m = (wid >> 2) * 64;
    const int warp_n = (wid & 3) * 32;
    const int m0 = blockIdx.y * CMM;
    const int n0 = blockIdx.x * CNN;

    const __half* A  = (MODE == 1) ? g_CTXh : g_Xh;
    const __half* BT = (MODE == 1) ? g_WpTh : g_WaTh;

    float acc[4][4][4];
#pragma unroll
    for (int mt = 0; mt < 4; mt++)
#pragma unroll
        for (int nt = 0; nt < 4; nt++)
#pragma unroll
            for (int r = 0; r < 4; r++) acc[mt][nt][r] = 0.0f;

    // ldmatrix lane->matrix assignment
    const int lsel  = lane >> 3;         // octet 0..3
    const int lrow8 = lane & 7;
    // A x4: mats (m,bc),(m+8,bc),(m,bc+16),(m+8,bc+16)  [sel bit0->+8row, bit1->+16B]
    const int aRow    = warp_m + ((lsel & 1) << 3) + lrow8;
    const int aColOff = (lsel >> 1) << 4;
    // B x4 (two n-tiles): mats (n,bc),(n,bc+16),(n+8,bc),(n+8,bc+16)
    const int bRow    = warp_n + ((lsel >> 1) << 3) + lrow8;
    const int bColOff = (lsel & 1) << 4;

    // loaders: row = tid>>1 (128 rows), 4 chunks of 16B each for A and B
    const int lrow = tid >> 1;
    const int cb   = (tid & 1) * 4;
    const __half* gA = A  + (size_t)(m0 + lrow) * EMB;
    const __half* gB = BT + (size_t)(n0 + lrow) * EMB;

#define ISSUE(s_)                                                              \
    {                                                                          \
        uint32_t st = sb + (uint32_t)(((s_) % SPIPE) * STG_B);                 \
        const __half* ga = gA + (s_) * TKK;                                    \
        const __half* gb = gB + (s_) * TKK;                                    \
        _Pragma("unroll")                                                      \
        for (int c = 0; c < 4; c++) {                                          \
            cp16(st + swz(lrow, (cb + c) * 16), ga + (cb + c) * 8);            \
            cp16(st + A_BY + swz(lrow, (cb + c) * 16), gb + (cb + c) * 8);     \
        }                                                                      \
    }

    ISSUE(0); asm volatile("cp.async.commit_group;" ::: "memory");
    ISSUE(1); asm volatile("cp.async.commit_group;" ::: "memory");
    asm volatile("cp.async.wait_group 1;" ::: "memory");
    __syncthreads();

    for (int s = 0; s < NSTAGE; s++) {
        if (s + 2 < NSTAGE) ISSUE(s + 2);
        asm volatile("cp.async.commit_group;" ::: "memory");

        const uint32_t stA = sb + (uint32_t)((s % SPIPE) * STG_B);
        const uint32_t stB = stA + A_BY;
#pragma unroll
        for (int g = 0; g < 4; g++) {
            const int bc = 32 * g;
            uint32_t af[4][4], bf[2][4];
#pragma unroll
            for (int mt = 0; mt < 4; mt++)
                LDSM_X4(af[mt][0], af[mt][1], af[mt][2], af[mt][3],
                        stA + swz(aRow + mt * 16, bc + aColOff));
#pragma unroll
            for (int np = 0; np < 2; np++)
                LDSM_X4(bf[np][0], bf[np][1], bf[np][2], bf[np][3],
                        stB + swz(bRow + np * 16, bc + bColOff));
#pragma unroll
            for (int mt = 0; mt < 4; mt++)
#pragma unroll
                for (int nt = 0; nt < 4; nt++)
                    mma_f16(acc[mt][nt][0], acc[mt][nt][1],
                            acc[mt][nt][2], acc[mt][nt][3],
                            af[mt][0], af[mt][1], af[mt][2], af[mt][3],
                            bf[nt >> 1][(nt & 1) * 2], bf[nt >> 1][(nt & 1) * 2 + 1]);
        }
        asm volatile("cp.async.wait_group 1;" ::: "memory");
        __syncthreads();
    }
#undef ISSUE

#pragma unroll
    for (int mt = 0; mt < 4; mt++) {
        const int r0 = m0 + warp_m + mt * 16 + gid;
        const int r1 = r0 + 8;
#pragma unroll
        for (int nt = 0; nt < 4; nt++) {
            const int nb = n0 + warp_n + nt * 8;
            const int c  = nb + tig * 2;
            const float2 bv = *(const float2*)(bias + c);
            float2 o0, o1;
            o0.x = acc[mt][nt][0] + bv.x;
            o0.y = acc[mt][nt][1] + bv.y;
            o1.x = acc[mt][nt][2] + bv.x;
            o1.y = acc[mt][nt][3] + bv.y;
            if (MODE == 1) {
                *(float2*)(Cout + (size_t)r0 * EMB + c) = o0;
                *(float2*)(Cout + (size_t)r1 * EMB + c) = o1;
            } else {
                const int which = nb >> 10;
                const int e  = nb & 1023;
                const int h  = e >> 6;
                const int dd = (e & 63) + tig * 2;
                const int b0i = r0 >> 11, s0i = r0 & 2047;
                const int b1i = r1 >> 11, s1i = r1 & 2047;
                if (which == 2) {
                    __half* vb0 = g_Vth + ((size_t)(b0i * NHEAD + h) * HDIM + dd) * S_LEN;
                    __half* vb1 = g_Vth + ((size_t)(b1i * NHEAD + h) * HDIM + dd) * S_LEN;
                    vb0[s0i]          = __float2half_rn(o0.x);
                    vb0[S_LEN + s0i]  = __float2half_rn(o0.y);
                    vb1[s1i]          = __float2half_rn(o1.x);
                    vb1[S_LEN + s1i]  = __float2half_rn(o1.y);
                } else {
                    __half* dst = (which == 0) ? g_Qh : g_Kh;
                    *(__half2*)(dst + ((size_t)(b0i * NHEAD + h) * S_LEN + s0i) * HDIM + dd)
                        = __floats2half2_rn(o0.x, o0.y);
                    *(__half2*)(dst + ((size_t)(b1i * NHEAD + h) * S_LEN + s1i) * HDIM + dd)
                        = __floats2half2_rn(o1.x, o1.y);
                }
            }
        }
    }
}

// ---------------------------------------------------------------------------
// Flash attention (causal), fp16 mma + ldmatrix.
// CTA 256 thr / 8 warps, q-tile 128, k-tile 64, D=64. K/V double-buffered.
// ---------------------------------------------------------------------------
#define FQ_BY (128 * 128)               // Q tile 16KB
#define FK_BY (64 * 128)                // 8KB per K buffer
#define KOFF  FQ_BY
#define VOFF  (FQ_BY + 2 * FK_BY)
#define FLASH_SMEM (FQ_BY + 4 * FK_BY)  // 49152

__global__ void __launch_bounds__(256)
flash_h()
{
    extern __shared__ char smc[];
    const uint32_t sb = smem_u32(smc);
    const int tid  = threadIdx.x;
    const int wid  = tid >> 5;
    const int lane = tid & 31;
    const int gid  = lane >> 2;
    const int tig  = lane & 3;
    const int qt   = blockIdx.x;
    const int bh   = blockIdx.y;
    const int q0   = qt * 128;

    const __half* Qg = g_Qh  + (size_t)bh * S_LEN * HDIM;
    const __half* Kg = g_Kh  + (size_t)bh * S_LEN * HDIM;
    const __half* Vg = g_Vth + (size_t)bh * HDIM * S_LEN;

    const int lsel  = lane >> 3;
    const int lrow8 = lane & 7;
    // A x4 (Q): sel bit0->+8row, bit1->+16B
    const int aRow    = wid * 16 + ((lsel & 1) << 3) + lrow8;
    const int aColOff = (lsel >> 1) << 4;
    // B x4 (K/V, two n-tiles): sel bit1->+8row, bit0->+16B
    const int bRow    = ((lsel >> 1) << 3) + lrow8;
    const int bColOff = (lsel & 1) << 4;

    // Q load
    {
        const int r = tid >> 1, c0 = (tid & 1) * 4;
        const __half* gq = Qg + (size_t)(q0 + r) * HDIM;
#pragma unroll
        for (int c = 0; c < 4; c++)
            cp16(sb + swz(r, (c0 + c) * 16), gq + (c0 + c) * 8);
    }

#define ISSUE_KV(kt_, buf_)                                                    \
    {                                                                          \
        const int r = tid >> 2, c0 = (tid & 3) * 2;                            \
        const __half* gk = Kg + (size_t)((kt_) * 64 + r) * HDIM;               \
        const __half* gv = Vg + (size_t)r * S_LEN + (kt_) * 64;                \
        _Pragma("unroll")                                                      \
        for (int c = 0; c < 2; c++) {                                          \
            cp16(sb + KOFF + (buf_) * FK_BY + swz(r, (c0 + c) * 16),           \
                 gk + (c0 + c) * 8);                                           \
            cp16(sb + VOFF + (buf_) * FK_BY + swz(r, (c0 + c) * 16),           \
                 gv + (c0 + c) * 8);                                           \
        }                                                                      \
    }

    ISSUE_KV(0, 0);
    asm volatile("cp.async.commit_group;" ::: "memory");
    asm volatile("cp.async.wait_group 0;" ::: "memory");
    __syncthreads();

    // Q A-fragments via ldmatrix
    uint32_t qa[4][4];
#pragma unroll
    for (int g = 0; g < 4; g++)
        LDSM_X4(qa[g][0], qa[g][1], qa[g][2], qa[g][3],
                sb + swz(aRow, 32 * g + aColOff));

    float m0v = -1e30f, m1v = -1e30f, l0 = 0.0f, l1 = 0.0f;
    float o[8][4];
#pragma unroll
    for (int nt = 0; nt < 8; nt++)
#pragma unroll
        for (int r = 0; r < 4; r++) o[nt][r] = 0.0f;

    const int r0g = q0 + wid * 16 + gid;
    const int nkt = 2 * (qt + 1);

    for (int kt = 0; kt < nkt; kt++) {
        asm volatile("cp.async.wait_group 0;" ::: "memory");
        __syncthreads();
        if (kt + 1 < nkt) ISSUE_KV(kt + 1, (kt + 1) & 1);
        asm volatile("cp.async.commit_group;" ::: "memory");

        const uint32_t Ks = sb + KOFF + (uint32_t)((kt & 1) * FK_BY);
        const uint32_t Vs = sb + VOFF + (uint32_t)((kt & 1) * FK_BY);
        const int k0 = kt * 64;

        float s[8][4];
#pragma unroll
        for (int nt = 0; nt < 8; nt++)
#pragma unroll
            for (int r = 0; r < 4; r++) s[nt][r] = 0.0f;

#pragma unroll
        for (int g = 0; g < 4; g++) {
            const int bc = 32 * g;
#pragma unroll
            for (int np = 0; np < 4; np++) {
                uint32_t bf[4];
                LDSM_X4(bf[0], bf[1], bf[2], bf[3],
                        Ks + swz(bRow + np * 16, bc + bColOff));
                mma_f16(s[2 * np][0], s[2 * np][1], s[2 * np][2], s[2 * np][3],
                        qa[g][0], qa[g][1], qa[g][2], qa[g][3], bf[0], bf[1]);
                mma_f16(s[2 * np + 1][0], s[2 * np + 1][1],
                        s[2 * np + 1][2], s[2 * np + 1][3],
                        qa[g][0], qa[g][1], qa[g][2], qa[g][3], bf[2], bf[3]);
            }
        }

        const bool domask = (k0 + 63) > r0g;
#pragma unroll
        for (int nt = 0; nt < 8; nt++) {
            const int c0 = k0 + nt * 8 + tig * 2;
            s[nt][0] *= 0.125f; s[nt][1] *= 0.125f;
            s[nt][2] *= 0.125f; s[nt][3] *= 0.125f;
            if (domask) {
                if (c0 > r0g)         s[nt][0] = -1e30f;
                if (c0 + 1 > r0g)     s[nt][1] = -1e30f;
                if (c0 > r0g + 8)     s[nt][2] = -1e30f;
                if (c0 + 1 > r0g + 8) s[nt][3] = -1e30f;
            }
        }

        float mx0 = -1e30f, mx1 = -1e30f;
#pragma unroll
        for (int nt = 0; nt < 8; nt++) {
            mx0 = fmaxf(mx0, fmaxf(s[nt][0], s[nt][1]));
            mx1 = fmaxf(mx1, fmaxf(s[nt][2], s[nt][3]));
        }
        mx0 = fmaxf(mx0, __shfl_xor_sync(0xffffffffu, mx0, 1));
        mx0 = fmaxf(mx0, __shfl_xor_sync(0xffffffffu, mx0, 2));
        mx1 = fmaxf(mx1, __shfl_xor_sync(0xffffffffu, mx1, 1));
        mx1 = fmaxf(mx1, __shfl_xor_sync(0xffffffffu, mx1, 2));

        const float mn0 = fmaxf(m0v, mx0);
        const float mn1 = fmaxf(m1v, mx1);
        const float al0 = __expf(m0v - mn0);
        const float al1 = __expf(m1v - mn1);
        m0v = mn0; m1v = mn1;

        uint32_t ph[8][2];
        float sum0 = 0.0f, sum1 = 0.0f;
#pragma unroll
        for (int nt = 0; nt < 8; nt++) {
            __half2 h01 = __floats2half2_rn(__expf(s[nt][0] - mn0),
                                            __expf(s[nt][1] - mn0));
            __half2 h23 = __floats2half2_rn(__expf(s[nt][2] - mn1),
                                            __expf(s[nt][3] - mn1));
            ph[nt][0] = h2u(h01);
            ph[nt][1] = h2u(h23);
            float2 f01 = __half22float2(h01);
            float2 f23 = __half22float2(h23);
            sum0 += f01.x + f01.y;
            sum1 += f23.x + f23.y;
        }
        sum0 += __shfl_xor_sync(0xffffffffu, sum0, 1);
        sum0 += __shfl_xor_sync(0xffffffffu, sum0, 2);
        sum1 += __shfl_xor_sync(0xffffffffu, sum1, 1);
        sum1 += __shfl_xor_sync(0xffffffffu, sum1, 2);
        l0 = l0 * al0 + sum0;
        l1 = l1 * al1 + sum1;

#pragma unroll
        for (int nt = 0; nt < 8; nt++) {
            o[nt][0] *= al0; o[nt][1] *= al0;
            o[nt][2] *= al1; o[nt][3] *= al1;
        }

        // O += P V
#pragma unroll
        for (int g = 0; g < 4; g++) {
            const int bc = 32 * g;
#pragma unroll
            for (int np = 0; np < 4; np++) {
                uint32_t bf[4];
                LDSM_X4(bf[0], bf[1], bf[2], bf[3],
                        Vs + swz(bRow + np * 16, bc + bColOff));
                mma_f16(o[2 * np][0], o[2 * np][1], o[2 * np][2], o[2 * np][3],
                        ph[2 * g][0], ph[2 * g][1],
                        ph[2 * g + 1][0], ph[2 * g + 1][1], bf[0], bf[1]);
                mma_f16(o[2 * np + 1][0], o[2 * np + 1][1],
                        o[2 * np + 1][2], o[2 * np + 1][3],
                        ph[2 * g][0], ph[2 * g][1],
                        ph[2 * g + 1][0], ph[2 * g + 1][1], bf[2], bf[3]);
            }
        }
    }
#undef ISSUE_KV

    // write ctx fp16
    const int b = bh >> 4, h = bh & 15;
    const float inv0 = 1.0f / l0;
    const float inv1 = 1.0f / l1;
    const int r1g = r0g + 8;
#pragma unroll
    for (int nt = 0; nt < 8; nt++) {
        const int col = h * HDIM + nt * 8 + tig * 2;
        *(__half2*)(g_CTXh + ((size_t)(b * S_LEN + r0g)) * EMB + col)
            = __floats2half2_rn(o[nt][0] * inv0, o[nt][1] * inv0);
        *(__half2*)(g_CTXh + ((size_t)(b * S_LEN + r1g)) * EMB + col)
            = __floats2half2_rn(o[nt][2] * inv1, o[nt][3] * inv1);
    }
}

// ---------------------------------------------------------------------------
extern "C" void kernel_launch(void* const* d_in, const int* in_sizes, int n_in,
                              void* d_out, int out_size)
{
    const float* x      = (const float*)d_in[0];
    const float* w_attn = (const float*)d_in[1];
    const float* b_attn = (const float*)d_in[2];
    const float* w_proj = (const float*)d_in[3];
    const float* b_proj = (const float*)d_in[4];
    float* out = (float*)d_out;

    cudaFuncSetAttribute(gemm_h<0>, cudaFuncAttributeMaxDynamicSharedMemorySize, GSMEM_BYTES);
    cudaFuncSetAttribute(gemm_h<1>, cudaFuncAttributeMaxDynamicSharedMemorySize, GSMEM_BYTES);
    cudaFuncSetAttribute(flash_h,   cudaFuncAttributeMaxDynamicSharedMemorySize, FLASH_SMEM);

    cvt_x<<<ROWS * EMB / 4 / 256, 256>>>(x);
    transpose_h<0><<<dim3(3 * EMB / 32, EMB / 32), dim3(32, 8)>>>(w_attn, EMB, 3 * EMB);
    transpose_h<1><<<dim3(EMB / 32, EMB / 32),     dim3(32, 8)>>>(w_proj, EMB, EMB);

    gemm_h<0><<<dim3(3 * EMB / CNN, ROWS / CMM), 256, GSMEM_BYTES>>>(b_attn, nullptr);
    flash_h<<<dim3(S_LEN / 128, B_SZ * NHEAD), 256, FLASH_SMEM>>>();
    gemm_h<1><<<dim3(EMB / CNN, ROWS / CMM), 256, GSMEM_BYTES>>>(b_proj, out);
}

// round 10
// speedup vs baseline: 6.1267x; 1.0124x over previous
#include <cuda_runtime.h>
#include <cuda_fp16.h>
#include <cstdint>
#include <math.h>

// Problem constants
#define B_SZ   2
#define S_LEN  2048
#define EMB    1024
#define NHEAD  16
#define HDIM   64
#define ROWS   (B_SZ * S_LEN)          // 4096

// Scratch (device globals -> no allocation). All fp16 operand tensors.
__device__ __half g_Qh [B_SZ * NHEAD * S_LEN * HDIM];   // [b,h,s,d]
__device__ __half g_Kh [B_SZ * NHEAD * S_LEN * HDIM];   // [b,h,s,d]
__device__ __half g_Vth[B_SZ * NHEAD * HDIM * S_LEN];   // [b,h,d,s]  (transposed!)
__device__ __half g_CTXh[ROWS * EMB];
__device__ __half g_Xh  [ROWS * EMB];
__device__ __half g_WaTh[3 * EMB * EMB];                // w_attn^T [3072][1024]
__device__ __half g_WpTh[EMB * EMB];                    // w_proj^T [1024][1024]

// ---------------------------------------------------------------------------
// Helpers
// ---------------------------------------------------------------------------
__device__ __forceinline__ uint32_t smem_u32(const void* p) {
    uint32_t a;
    asm("{ .reg .u64 t; cvta.to.shared.u64 t, %1; cvt.u32.u64 %0, t; }"
        : "=r"(a) : "l"(p));
    return a;
}
__device__ __forceinline__ void cp16(uint32_t smaddr, const void* gaddr) {
    asm volatile("cp.async.cg.shared.global [%0], [%1], 16;"
                 :: "r"(smaddr), "l"(gaddr) : "memory");
}
__device__ __forceinline__ uint32_t h2u(__half2 h) {
    return *reinterpret_cast<uint32_t*>(&h);
}
__device__ __forceinline__ void mma_f16(float& d0, float& d1, float& d2, float& d3,
                                        uint32_t a0, uint32_t a1, uint32_t a2, uint32_t a3,
                                        uint32_t b0, uint32_t b1) {
    asm volatile(
        "mma.sync.aligned.m16n8k16.row.col.f32.f16.f16.f32 "
        "{%0,%1,%2,%3},{%4,%5,%6,%7},{%8,%9},{%0,%1,%2,%3};"
        : "+f"(d0), "+f"(d1), "+f"(d2), "+f"(d3)
        : "r"(a0), "r"(a1), "r"(a2), "r"(a3), "r"(b0), "r"(b1));
}
#define LDSM_X4(r0, r1, r2, r3, addr)                                          \
    asm volatile("ldmatrix.sync.aligned.m8n8.x4.shared.b16 {%0,%1,%2,%3}, [%4];" \
                 : "=r"(r0), "=r"(r1), "=r"(r2), "=r"(r3) : "r"(addr))

// XOR swizzle within a 128B row: 16B chunk index ^ (row & 7)
__device__ __forceinline__ uint32_t swz(int row, int bc) {
    return (uint32_t)(row * 128 + (((bc >> 4) ^ (row & 7)) << 4) + (bc & 15));
}

// ---------------------------------------------------------------------------
// Fused prep: x -> fp16 copy, plus both weight transposes (fp32->fp16).
// Grid layout: [0, 4096)          cvt_x      (256 thr, 1024 elems each)
//              [4096, 4096+3072)  transpose w_attn  (32x32 tile per block)
//              [7168, 7168+1024)  transpose w_proj
// ---------------------------------------------------------------------------
#define PREP_CVT_BLOCKS 4096
#define PREP_WA_BLOCKS  3072           // (3072/32) * (1024/32)
#define PREP_WP_BLOCKS  1024           // (1024/32) * (1024/32)
#define PREP_BLOCKS (PREP_CVT_BLOCKS + PREP_WA_BLOCKS + PREP_WP_BLOCKS)

__global__ void prep_all(const float* __restrict__ x,
                         const float* __restrict__ w_attn,
                         const float* __restrict__ w_proj)
{
    const int bid = blockIdx.x;
    if (bid < PREP_CVT_BLOCKS) {
        int i = (bid * 256 + threadIdx.x) * 4;
        float4 v = *(const float4*)(x + i);
        __half2* o = (__half2*)(g_Xh + i);
        o[0] = __floats2half2_rn(v.x, v.y);
        o[1] = __floats2half2_rn(v.z, v.w);
        return;
    }
    __shared__ float t[32][33];
    const float* src;
    __half* dst;
    int N, nblk_x, tb;
    if (bid < PREP_CVT_BLOCKS + PREP_WA_BLOCKS) {
        tb = bid - PREP_CVT_BLOCKS;
        src = w_attn; dst = g_WaTh; N = 3 * EMB; nblk_x = (3 * EMB) / 32;
    } else {
        tb = bid - PREP_CVT_BLOCKS - PREP_WA_BLOCKS;
        src = w_proj; dst = g_WpTh; N = EMB; nblk_x = EMB / 32;
    }
    const int K = EMB;
    const int x_ = threadIdx.x & 31, y_ = threadIdx.x >> 5;
    const int n0 = (tb % nblk_x) * 32, k0 = (tb / nblk_x) * 32;
#pragma unroll
    for (int i = 0; i < 4; i++)
        t[y_ + i * 8][x_] = src[(size_t)(k0 + y_ + i * 8) * N + n0 + x_];
    __syncthreads();
#pragma unroll
    for (int i = 0; i < 4; i++)
        dst[(size_t)(n0 + y_ + i * 8) * K + k0 + x_] = __float2half_rn(t[x_][y_ + i * 8]);
}

// ---------------------------------------------------------------------------
// fp16 mma.sync GEMM with ldmatrix fragment loads.
// CTA 128x128, 8 warps (2x4, warp 64x32), TK=64, 3-stage cp.async.
// ---------------------------------------------------------------------------
#define CMM 128
#define CNN 128
#define TKK 64
#define A_BY (CMM * TKK * 2)            // 16384
#define STG_B (2 * A_BY)                // 32768
#define SPIPE 3
#define GSMEM_BYTES (SPIPE * STG_B)     // 98304
#define NSTAGE (EMB / TKK)              // 16

template <int MODE>
__global__ void __launch_bounds__(256, 2)
gemm_h(const float* __restrict__ bias, float* __restrict__ Cout)
{
    extern __shared__ char smc[];
    const uint32_t sb = smem_u32(smc);
    const int tid  = threadIdx.x;
    const int wid  = tid >> 5;
    const int lane = tid & 31;
    const int gid  = lane >> 2;
    const int tig  = lane & 3;
    const int warp_m = (wid >> 2) * 64;
    const int warp_n = (wid & 3) * 32;
    const int m0 = blockIdx.y * CMM;
    const int n0 = blockIdx.x * CNN;

    const __half* A  = (MODE == 1) ? g_CTXh : g_Xh;
    const __half* BT = (MODE == 1) ? g_WpTh : g_WaTh;

    float acc[4][4][4];
#pragma unroll
    for (int mt = 0; mt < 4; mt++)
#pragma unroll
        for (int nt = 0; nt < 4; nt++)
#pragma unroll
            for (int r = 0; r < 4; r++) acc[mt][nt][r] = 0.0f;

    const int lsel  = lane >> 3;
    const int lrow8 = lane & 7;
    const int aRow    = warp_m + ((lsel & 1) << 3) + lrow8;
    const int aColOff = (lsel >> 1) << 4;
    const int bRow    = warp_n + ((lsel >> 1) << 3) + lrow8;
    const int bColOff = (lsel & 1) << 4;

    const int lrow = tid >> 1;
    const int cb   = (tid & 1) * 4;
    const __half* gA = A  + (size_t)(m0 + lrow) * EMB;
    const __half* gB = BT + (size_t)(n0 + lrow) * EMB;

#define ISSUE(s_)                                                              \
    {                                                                          \
        uint32_t st = sb + (uint32_t)(((s_) % SPIPE) * STG_B);                 \
        const __half* ga = gA + (s_) * TKK;                                    \
        const __half* gb = gB + (s_) * TKK;                                    \
        _Pragma("unroll")                                                      \
        for (int c = 0; c < 4; c++) {                                          \
            cp16(st + swz(lrow, (cb + c) * 16), ga + (cb + c) * 8);            \
            cp16(st + A_BY + swz(lrow, (cb + c) * 16), gb + (cb + c) * 8);     \
        }                                                                      \
    }

    ISSUE(0); asm volatile("cp.async.commit_group;" ::: "memory");
    ISSUE(1); asm volatile("cp.async.commit_group;" ::: "memory");
    asm volatile("cp.async.wait_group 1;" ::: "memory");
    __syncthreads();

    for (int s = 0; s < NSTAGE; s++) {
        if (s + 2 < NSTAGE) ISSUE(s + 2);
        asm volatile("cp.async.commit_group;" ::: "memory");

        const uint32_t stA = sb + (uint32_t)((s % SPIPE) * STG_B);
        const uint32_t stB = stA + A_BY;
#pragma unroll
        for (int g = 0; g < 4; g++) {
            const int bc = 32 * g;
            uint32_t af[4][4], bf[2][4];
#pragma unroll
            for (int mt = 0; mt < 4; mt++)
                LDSM_X4(af[mt][0], af[mt][1], af[mt][2], af[mt][3],
                        stA + swz(aRow + mt * 16, bc + aColOff));
#pragma unroll
            for (int np = 0; np < 2; np++)
                LDSM_X4(bf[np][0], bf[np][1], bf[np][2], bf[np][3],
                        stB + swz(bRow + np * 16, bc + bColOff));
#pragma unroll
            for (int mt = 0; mt < 4; mt++)
#pragma unroll
                for (int nt = 0; nt < 4; nt++)
                    mma_f16(acc[mt][nt][0], acc[mt][nt][1],
                            acc[mt][nt][2], acc[mt][nt][3],
                            af[mt][0], af[mt][1], af[mt][2], af[mt][3],
                            bf[nt >> 1][(nt & 1) * 2], bf[nt >> 1][(nt & 1) * 2 + 1]);
        }
        asm volatile("cp.async.wait_group 1;" ::: "memory");
        __syncthreads();
    }
#undef ISSUE

#pragma unroll
    for (int mt = 0; mt < 4; mt++) {
        const int r0 = m0 + warp_m + mt * 16 + gid;
        const int r1 = r0 + 8;
#pragma unroll
        for (int nt = 0; nt < 4; nt++) {
            const int nb = n0 + warp_n + nt * 8;
            const int c  = nb + tig * 2;
            const float2 bv = *(const float2*)(bias + c);
            float2 o0, o1;
            o0.x = acc[mt][nt][0] + bv.x;
            o0.y = acc[mt][nt][1] + bv.y;
            o1.x = acc[mt][nt][2] + bv.x;
            o1.y = acc[mt][nt][3] + bv.y;
            if (MODE == 1) {
                *(float2*)(Cout + (size_t)r0 * EMB + c) = o0;
                *(float2*)(Cout + (size_t)r1 * EMB + c) = o1;
            } else {
                const int which = nb >> 10;
                const int e  = nb & 1023;
                const int h  = e >> 6;
                const int dd = (e & 63) + tig * 2;
                const int b0i = r0 >> 11, s0i = r0 & 2047;
                const int b1i = r1 >> 11, s1i = r1 & 2047;
                if (which == 2) {
                    __half* vb0 = g_Vth + ((size_t)(b0i * NHEAD + h) * HDIM + dd) * S_LEN;
                    __half* vb1 = g_Vth + ((size_t)(b1i * NHEAD + h) * HDIM + dd) * S_LEN;
                    vb0[s0i]          = __float2half_rn(o0.x);
                    vb0[S_LEN + s0i]  = __float2half_rn(o0.y);
                    vb1[s1i]          = __float2half_rn(o1.x);
                    vb1[S_LEN + s1i]  = __float2half_rn(o1.y);
                } else {
                    __half* dst = (which == 0) ? g_Qh : g_Kh;
                    *(__half2*)(dst + ((size_t)(b0i * NHEAD + h) * S_LEN + s0i) * HDIM + dd)
                        = __floats2half2_rn(o0.x, o0.y);
                    *(__half2*)(dst + ((size_t)(b1i * NHEAD + h) * S_LEN + s1i) * HDIM + dd)
                        = __floats2half2_rn(o1.x, o1.y);
                }
            }
        }
    }
}

// ---------------------------------------------------------------------------
// Flash attention (causal), fp16 mma + ldmatrix.
// CTA 256 thr / 8 warps, q-tile 128, k-tile 64, D=64. K/V double-buffered.
// 2 CTAs/SM (forced) + reversed qt order (heavy CTAs scheduled first).
// ---------------------------------------------------------------------------
#define FQ_BY (128 * 128)               // Q tile 16KB
#define FK_BY (64 * 128)                // 8KB per K buffer
#define KOFF  FQ_BY
#define VOFF  (FQ_BY + 2 * FK_BY)
#define FLASH_SMEM (FQ_BY + 4 * FK_BY)  // 49152

__global__ void __launch_bounds__(256, 2)
flash_h()
{
    extern __shared__ char smc[];
    const uint32_t sb = smem_u32(smc);
    const int tid  = threadIdx.x;
    const int wid  = tid >> 5;
    const int lane = tid & 31;
    const int gid  = lane >> 2;
    const int tig  = lane & 3;
    const int qt   = gridDim.x - 1 - blockIdx.x;   // heavy tiles first
    const int bh   = blockIdx.y;
    const int q0   = qt * 128;

    const __half* Qg = g_Qh  + (size_t)bh * S_LEN * HDIM;
    const __half* Kg = g_Kh  + (size_t)bh * S_LEN * HDIM;
    const __half* Vg = g_Vth + (size_t)bh * HDIM * S_LEN;

    const int lsel  = lane >> 3;
    const int lrow8 = lane & 7;
    const int aRow    = wid * 16 + ((lsel & 1) << 3) + lrow8;
    const int aColOff = (lsel >> 1) << 4;
    const int bRow    = ((lsel >> 1) << 3) + lrow8;
    const int bColOff = (lsel & 1) << 4;

    // Q load
    {
        const int r = tid >> 1, c0 = (tid & 1) * 4;
        const __half* gq = Qg + (size_t)(q0 + r) * HDIM;
#pragma unroll
        for (int c = 0; c < 4; c++)
            cp16(sb + swz(r, (c0 + c) * 16), gq + (c0 + c) * 8);
    }

#define ISSUE_KV(kt_, buf_)                                                    \
    {                                                                          \
        const int r = tid >> 2, c0 = (tid & 3) * 2;                            \
        const __half* gk = Kg + (size_t)((kt_) * 64 + r) * HDIM;               \
        const __half* gv = Vg + (size_t)r * S_LEN + (kt_) * 64;                \
        _Pragma("unroll")                                                      \
        for (int c = 0; c < 2; c++) {                                          \
            cp16(sb + KOFF + (buf_) * FK_BY + swz(r, (c0 + c) * 16),           \
                 gk + (c0 + c) * 8);                                           \
            cp16(sb + VOFF + (buf_) * FK_BY + swz(r, (c0 + c) * 16),           \
                 gv + (c0 + c) * 8);                                           \
        }                                                                      \
    }

    ISSUE_KV(0, 0);
    asm volatile("cp.async.commit_group;" ::: "memory");
    asm volatile("cp.async.wait_group 0;" ::: "memory");
    __syncthreads();

    // Q A-fragments via ldmatrix
    uint32_t qa[4][4];
#pragma unroll
    for (int g = 0; g < 4; g++)
        LDSM_X4(qa[g][0], qa[g][1], qa[g][2], qa[g][3],
                sb + swz(aRow, 32 * g + aColOff));

    float m0v = -1e30f, m1v = -1e30f, l0 = 0.0f, l1 = 0.0f;
    float o[8][4];
#pragma unroll
    for (int nt = 0; nt < 8; nt++)
#pragma unroll
        for (int r = 0; r < 4; r++) o[nt][r] = 0.0f;

    const int r0g = q0 + wid * 16 + gid;
    const int nkt = 2 * (qt + 1);

    for (int kt = 0; kt < nkt; kt++) {
        asm volatile("cp.async.wait_group 0;" ::: "memory");
        __syncthreads();
        if (kt + 1 < nkt) ISSUE_KV(kt + 1, (kt + 1) & 1);
        asm volatile("cp.async.commit_group;" ::: "memory");

        const uint32_t Ks = sb + KOFF + (uint32_t)((kt & 1) * FK_BY);
        const uint32_t Vs = sb + VOFF + (uint32_t)((kt & 1) * FK_BY);
        const int k0 = kt * 64;

        float s[8][4];
#pragma unroll
        for (int nt = 0; nt < 8; nt++)
#pragma unroll
            for (int r = 0; r < 4; r++) s[nt][r] = 0.0f;

#pragma unroll
        for (int g = 0; g < 4; g++) {
            const int bc = 32 * g;
#pragma unroll
            for (int np = 0; np < 4; np++) {
                uint32_t bf[4];
                LDSM_X4(bf[0], bf[1], bf[2], bf[3],
                        Ks + swz(bRow + np * 16, bc + bColOff));
                mma_f16(s[2 * np][0], s[2 * np][1], s[2 * np][2], s[2 * np][3],
                        qa[g][0], qa[g][1], qa[g][2], qa[g][3], bf[0], bf[1]);
                mma_f16(s[2 * np + 1][0], s[2 * np + 1][1],
                        s[2 * np + 1][2], s[2 * np + 1][3],
                        qa[g][0], qa[g][1], qa[g][2], qa[g][3], bf[2], bf[3]);
            }
        }

        const bool domask = (k0 + 63) > r0g;
#pragma unroll
        for (int nt = 0; nt < 8; nt++) {
            const int c0 = k0 + nt * 8 + tig * 2;
            s[nt][0] *= 0.125f; s[nt][1] *= 0.125f;
            s[nt][2] *= 0.125f; s[nt][3] *= 0.125f;
            if (domask) {
                if (c0 > r0g)         s[nt][0] = -1e30f;
                if (c0 + 1 > r0g)     s[nt][1] = -1e30f;
                if (c0 > r0g + 8)     s[nt][2] = -1e30f;
                if (c0 + 1 > r0g + 8) s[nt][3] = -1e30f;
            }
        }

        float mx0 = -1e30f, mx1 = -1e30f;
#pragma unroll
        for (int nt = 0; nt < 8; nt++) {
            mx0 = fmaxf(mx0, fmaxf(s[nt][0], s[nt][1]));
            mx1 = fmaxf(mx1, fmaxf(s[nt][2], s[nt][3]));
        }
        mx0 = fmaxf(mx0, __shfl_xor_sync(0xffffffffu, mx0, 1));
        mx0 = fmaxf(mx0, __shfl_xor_sync(0xffffffffu, mx0, 2));
        mx1 = fmaxf(mx1, __shfl_xor_sync(0xffffffffu, mx1, 1));
        mx1 = fmaxf(mx1, __shfl_xor_sync(0xffffffffu, mx1, 2));

        const float mn0 = fmaxf(m0v, mx0);
        const float mn1 = fmaxf(m1v, mx1);
        const float al0 = __expf(m0v - mn0);
        const float al1 = __expf(m1v - mn1);
        m0v = mn0; m1v = mn1;

        uint32_t ph[8][2];
        float sum0 = 0.0f, sum1 = 0.0f;
#pragma unroll
        for (int nt = 0; nt < 8; nt++) {
            __half2 h01 = __floats2half2_rn(__expf(s[nt][0] - mn0),
                                            __expf(s[nt][1] - mn0));
            __half2 h23 = __floats2half2_rn(__expf(s[nt][2] - mn1),
                                            __expf(s[nt][3] - mn1));
            ph[nt][0] = h2u(h01);
            ph[nt][1] = h2u(h23);
            float2 f01 = __half22float2(h01);
            float2 f23 = __half22float2(h23);
            sum0 += f01.x + f01.y;
            sum1 += f23.x + f23.y;
        }
        sum0 += __shfl_xor_sync(0xffffffffu, sum0, 1);
        sum0 += __shfl_xor_sync(0xffffffffu, sum0, 2);
        sum1 += __shfl_xor_sync(0xffffffffu, sum1, 1);
        sum1 += __shfl_xor_sync(0xffffffffu, sum1, 2);
        l0 = l0 * al0 + sum0;
        l1 = l1 * al1 + sum1;

#pragma unroll
        for (int nt = 0; nt < 8; nt++) {
            o[nt][0] *= al0; o[nt][1] *= al0;
            o[nt][2] *= al1; o[nt][3] *= al1;
        }

        // O += P V
#pragma unroll
        for (int g = 0; g < 4; g++) {
            const int bc = 32 * g;
#pragma unroll
            for (int np = 0; np < 4; np++) {
                uint32_t bf[4];
                LDSM_X4(bf[0], bf[1], bf[2], bf[3],
                        Vs + swz(bRow + np * 16, bc + bColOff));
                mma_f16(o[2 * np][0], o[2 * np][1], o[2 * np][2], o[2 * np][3],
                        ph[2 * g][0], ph[2 * g][1],
                        ph[2 * g + 1][0], ph[2 * g + 1][1], bf[0], bf[1]);
                mma_f16(o[2 * np + 1][0], o[2 * np + 1][1],
                        o[2 * np + 1][2], o[2 * np + 1][3],
                        ph[2 * g][0], ph[2 * g][1],
                        ph[2 * g + 1][0], ph[2 * g + 1][1], bf[2], bf[3]);
            }
        }
    }
#undef ISSUE_KV

    // write ctx fp16
    const int b = bh >> 4, h = bh & 15;
    const float inv0 = 1.0f / l0;
    const float inv1 = 1.0f / l1;
    const int r1g = r0g + 8;
#pragma unroll
    for (int nt = 0; nt < 8; nt++) {
        const int col = h * HDIM + nt * 8 + tig * 2;
        *(__half2*)(g_CTXh + ((size_t)(b * S_LEN + r0g)) * EMB + col)
            = __floats2half2_rn(o[nt][0] * inv0, o[nt][1] * inv0);
        *(__half2*)(g_CTXh + ((size_t)(b * S_LEN + r1g)) * EMB + col)
            = __floats2half2_rn(o[nt][2] * inv1, o[nt][3] * inv1);
    }
}

// ---------------------------------------------------------------------------
extern "C" void kernel_launch(void* const* d_in, const int* in_sizes, int n_in,
                              void* d_out, int out_size)
{
    const float* x      = (const float*)d_in[0];
    const float* w_attn = (const float*)d_in[1];
    const float* b_attn = (const float*)d_in[2];
    const float* w_proj = (const float*)d_in[3];
    const float* b_proj = (const float*)d_in[4];
    float* out = (float*)d_out;

    cudaFuncSetAttribute(gemm_h<0>, cudaFuncAttributeMaxDynamicSharedMemorySize, GSMEM_BYTES);
    cudaFuncSetAttribute(gemm_h<1>, cudaFuncAttributeMaxDynamicSharedMemorySize, GSMEM_BYTES);
    cudaFuncSetAttribute(flash_h,   cudaFuncAttributeMaxDynamicSharedMemorySize, FLASH_SMEM);

    // 0) fused prep: x->fp16 + both weight transposes
    prep_all<<<PREP_BLOCKS, 256>>>(x, w_attn, w_proj);

    // 1) QKV GEMM -> Q,K fp16 [s][d]; V fp16 [d][s]
    gemm_h<0><<<dim3(3 * EMB / CNN, ROWS / CMM), 256, GSMEM_BYTES>>>(b_attn, nullptr);

    // 2) causal flash attention (fp16 mma) -> g_CTXh
    flash_h<<<dim3(S_LEN / 128, B_SZ * NHEAD), 256, FLASH_SMEM>>>();

    // 3) projection GEMM -> out (fp32)
    gemm_h<1><<<dim3(EMB / CNN, ROWS / CMM), 256, GSMEM_BYTES>>>(b_proj, out);
}